// round 5
// baseline (speedup 1.0000x reference)
#include <cuda_runtime.h>
#include <math.h>

#define NCLS 19
#define DD   128
#define HWP  65536          // H*W
#define BB   8
#define NPIX (BB*HWP)       // 524288

#define PREP_THREADS 256
#define PREP_BLOCKS  (NPIX/4/PREP_THREADS)   // 512
#define P1_JQ      32
#define P1_SPLIT   8
#define P1_THREADS 128
#define P1_BLOCKS  (P1_JQ*BB*P1_SPLIT)       // 2048
#define P2_THREADS 256
#define NQ         (NPIX/4)                  // 131072 pixel-quads
#define P2_BLOCKS  (NQ/2/P2_THREADS)         // 256 per half

// ---- static scratch (no allocations allowed; zero-init at load) ----
__device__ float          g_sums[NCLS*DD];
__device__ float          g_means[NCLS*DD];
__device__ int            g_hist[PREP_BLOCKS*NCLS];
__device__ int            g_cnt[NCLS];
__device__ float          g_var[NCLS];
__device__ unsigned int   g_done0;
__device__ unsigned int   g_done1;
__device__ unsigned int   g_done2;
__device__ unsigned char  g_labs[NPIX];

// ------------------------------------------------------ label pack + hist
// 4 labels/thread via int4. Last block reduces g_hist -> g_cnt.
__global__ void __launch_bounds__(PREP_THREADS) k_prep(const int* __restrict__ labels) {
    __shared__ int hist[NCLS];
    int t = threadIdx.x;
    if (t < NCLS) hist[t] = 0;
    __syncthreads();
    int q = blockIdx.x*PREP_THREADS + t;
    int4 lv = ((const int4*)labels)[q];
    uchar4 u;
    u.x = (lv.x >= 0 && lv.x < NCLS) ? (unsigned char)lv.x : (unsigned char)255;
    u.y = (lv.y >= 0 && lv.y < NCLS) ? (unsigned char)lv.y : (unsigned char)255;
    u.z = (lv.z >= 0 && lv.z < NCLS) ? (unsigned char)lv.z : (unsigned char)255;
    u.w = (lv.w >= 0 && lv.w < NCLS) ? (unsigned char)lv.w : (unsigned char)255;
    ((uchar4*)g_labs)[q] = u;
    if (u.x < NCLS) atomicAdd(&hist[u.x], 1);
    if (u.y < NCLS) atomicAdd(&hist[u.y], 1);
    if (u.z < NCLS) atomicAdd(&hist[u.z], 1);
    if (u.w < NCLS) atomicAdd(&hist[u.w], 1);
    __syncthreads();
    if (t < NCLS) g_hist[blockIdx.x*NCLS + t] = hist[t];

    __threadfence();
    __shared__ bool isLast;
    if (t == 0) isLast = (atomicAdd(&g_done0, 1u) == PREP_BLOCKS - 1);
    __syncthreads();
    if (!isLast) return;

    __shared__ int scnt[NCLS];
    if (t < NCLS) scnt[t] = 0;
    __syncthreads();
    {
        const int R = PREP_BLOCKS / PREP_THREADS;   // 2 rows/thread
        int loc[NCLS];
        #pragma unroll
        for (int c = 0; c < NCLS; c++) loc[c] = 0;
        const int* rows = &g_hist[t * R * NCLS];
        for (int r = 0; r < R; r++)
            #pragma unroll
            for (int c = 0; c < NCLS; c++) loc[c] += rows[r*NCLS + c];
        #pragma unroll
        for (int c = 0; c < NCLS; c++) atomicAdd(&scnt[c], loc[c]);
    }
    __syncthreads();
    if (t < NCLS) g_cnt[t] = scnt[t];
    if (t == 0) g_done0 = 0u;
}

// ---------------------------------------------------------------- pass 1
// Each thread owns a fixed d-quad (d0..d0+3). One label test guards TWO
// packed f32x2 adds (4 elements). No manual prefetch (register pressure);
// ptxas pipelines. Last block computes means, resets scratch.
__device__ __forceinline__ unsigned long long packf2(float lo, float hi) {
    unsigned long long v;
    asm("mov.b64 %0, {%1, %2};" : "=l"(v) : "f"(lo), "f"(hi));
    return v;
}

template<int CI>
__device__ __forceinline__ void step_all(unsigned long long* accA, unsigned long long* accB,
                                         unsigned long long vA, unsigned long long vB, int lab) {
    asm("{\n\t.reg .pred p;\n\t"
        "setp.eq.s32 p, %2, %3;\n\t"
        "@p add.rn.f32x2 %0, %0, %4;\n\t"
        "@p add.rn.f32x2 %1, %1, %5;\n\t}"
        : "+l"(accA[CI]), "+l"(accB[CI])
        : "r"(lab), "n"(CI), "l"(vA), "l"(vB));
    if constexpr (CI + 1 < NCLS) step_all<CI+1>(accA, accB, vA, vB, lab);
}

__global__ void __launch_bounds__(P1_THREADS) k_pass1(const float* __restrict__ feats) {
    int jq = blockIdx.x;            // d-quad index 0..31
    int b  = blockIdx.y;            // batch plane 0..7
    int s  = blockIdx.z;            // pixel split 0..7
    int d0 = jq * 4;
    const int nvec  = HWP / 4;          // 16384 float4 per plane
    const int chunk = nvec / P1_SPLIT;  // 2048
    const int base  = s * chunk;

    const float4* f0 = (const float4*)(feats + ((size_t)b*DD + d0    ) * HWP) + base;
    const float4* f1 = (const float4*)(feats + ((size_t)b*DD + d0 + 1) * HWP) + base;
    const float4* f2 = (const float4*)(feats + ((size_t)b*DD + d0 + 2) * HWP) + base;
    const float4* f3 = (const float4*)(feats + ((size_t)b*DD + d0 + 3) * HWP) + base;
    const uchar4* lb = (const uchar4*)(g_labs + (size_t)b*HWP) + base;

    unsigned long long accA[NCLS], accB[NCLS];
    #pragma unroll
    for (int c = 0; c < NCLS; c++) { accA[c] = 0ull; accB[c] = 0ull; }

    for (int i = threadIdx.x; i < chunk; i += P1_THREADS) {
        float4 a0 = f0[i];
        float4 a1 = f1[i];
        float4 a2 = f2[i];
        float4 a3 = f3[i];
        uchar4 l  = lb[i];
        step_all<0>(accA, accB, packf2(a0.x, a1.x), packf2(a2.x, a3.x), (int)l.x);
        step_all<0>(accA, accB, packf2(a0.y, a1.y), packf2(a2.y, a3.y), (int)l.y);
        step_all<0>(accA, accB, packf2(a0.z, a1.z), packf2(a2.z, a3.z), (int)l.z);
        step_all<0>(accA, accB, packf2(a0.w, a1.w), packf2(a2.w, a3.w), (int)l.w);
    }

    // block reduce: warp shuffle -> shared -> global atomics
    __shared__ float shred[NCLS*4];
    if (threadIdx.x < NCLS*4) shred[threadIdx.x] = 0.f;
    __syncthreads();
    int lane = threadIdx.x & 31;
    #pragma unroll
    for (int c = 0; c < NCLS; c++) {
        float x0, x1, x2, x3;
        asm("mov.b64 {%0, %1}, %2;" : "=f"(x0), "=f"(x1) : "l"(accA[c]));
        asm("mov.b64 {%0, %1}, %2;" : "=f"(x2), "=f"(x3) : "l"(accB[c]));
        #pragma unroll
        for (int o = 16; o; o >>= 1) {
            x0 += __shfl_down_sync(0xffffffffu, x0, o);
            x1 += __shfl_down_sync(0xffffffffu, x1, o);
            x2 += __shfl_down_sync(0xffffffffu, x2, o);
            x3 += __shfl_down_sync(0xffffffffu, x3, o);
        }
        if (lane == 0) {
            atomicAdd(&shred[c*4+0], x0);
            atomicAdd(&shred[c*4+1], x1);
            atomicAdd(&shred[c*4+2], x2);
            atomicAdd(&shred[c*4+3], x3);
        }
    }
    __syncthreads();
    if (threadIdx.x < NCLS*4) {
        int c = threadIdx.x >> 2, k = threadIdx.x & 3;
        atomicAdd(&g_sums[c*DD + d0 + k], shred[threadIdx.x]);
    }

    // ---- last-arriving block: means + scratch reset ----
    __threadfence();
    __shared__ bool isLast;
    if (threadIdx.x == 0) isLast = (atomicAdd(&g_done1, 1u) == P1_BLOCKS - 1);
    __syncthreads();
    if (!isLast) return;

    for (int idx = threadIdx.x; idx < NCLS*DD; idx += P1_THREADS) {
        int c = idx >> 7;
        g_means[idx] = g_sums[idx] / fmaxf((float)g_cnt[c], 1.f);
        g_sums[idx] = 0.f;                       // reset for next replay
    }
    if (threadIdx.x == 0) g_done1 = 0u;
}

// ---------------------------------------------------------------- pass 2
// 4 pixels/thread via float4; means in shared at stride 129 (conflict-free).
__device__ __forceinline__ void pass2_body(const float* __restrict__ feats, int q,
                                           const float* ms, float* vs) {
    int b  = q >> 14;                     // 16384 quads per batch plane
    int hq = q & 16383;
    const float4* fp = (const float4*)(feats + (size_t)b*DD*HWP) + hq;
    uchar4 l = ((const uchar4*)g_labs)[q];

    int l0 = l.x, l1 = l.y, l2 = l.z, l3 = l.w;
    const float* m0 = ms + (l0 < NCLS ? l0 : 0)*129;
    const float* m1 = ms + (l1 < NCLS ? l1 : 0)*129;
    const float* m2 = ms + (l2 < NCLS ? l2 : 0)*129;
    const float* m3 = ms + (l3 < NCLS ? l3 : 0)*129;

    float acc0 = 0.f, acc1 = 0.f, acc2 = 0.f, acc3 = 0.f;
    #pragma unroll 8
    for (int d = 0; d < DD; d++) {
        float4 v = fp[(size_t)d * (HWP/4)];
        float df;
        df = v.x - m0[d]; acc0 = fmaf(df, df, acc0);
        df = v.y - m1[d]; acc1 = fmaf(df, df, acc1);
        df = v.z - m2[d]; acc2 = fmaf(df, df, acc2);
        df = v.w - m3[d]; acc3 = fmaf(df, df, acc3);
    }
    if (l0 < NCLS) { float h = fmaxf(sqrtf(acc0) - 0.5f, 0.f); atomicAdd(&vs[l0], h*h); }
    if (l1 < NCLS) { float h = fmaxf(sqrtf(acc1) - 0.5f, 0.f); atomicAdd(&vs[l1], h*h); }
    if (l2 < NCLS) { float h = fmaxf(sqrtf(acc2) - 0.5f, 0.f); atomicAdd(&vs[l2], h*h); }
    if (l3 < NCLS) { float h = fmaxf(sqrtf(acc3) - 0.5f, 0.f); atomicAdd(&vs[l3], h*h); }
}

__global__ void __launch_bounds__(P2_THREADS) k_pass2a(const float* __restrict__ feats) {
    __shared__ float ms[NCLS*129];
    __shared__ float vs[NCLS];
    int t = threadIdx.x;
    for (int i = t; i < NCLS*DD; i += P2_THREADS)
        ms[(i >> 7)*129 + (i & 127)] = g_means[i];
    if (t < NCLS) vs[t] = 0.f;
    __syncthreads();
    pass2_body(feats, blockIdx.x*P2_THREADS + t, ms, vs);
    __syncthreads();
    if (t < NCLS) atomicAdd(&g_var[t], vs[t]);
}

__global__ void __launch_bounds__(P2_THREADS) k_pass2b(const float* __restrict__ feats,
                                                       float* __restrict__ out) {
    __shared__ float ms[NCLS*129];
    __shared__ float vs[NCLS];
    int t = threadIdx.x;
    for (int i = t; i < NCLS*DD; i += P2_THREADS)
        ms[(i >> 7)*129 + (i & 127)] = g_means[i];
    if (t < NCLS) vs[t] = 0.f;
    __syncthreads();
    pass2_body(feats, NQ/2 + blockIdx.x*P2_THREADS + t, ms, vs);
    __syncthreads();
    if (t < NCLS) atomicAdd(&g_var[t], vs[t]);

    // ---- last-arriving block (pass2a already complete: stream order) ----
    __threadfence();
    __shared__ bool isLast;
    if (t == 0) isLast = (atomicAdd(&g_done2, 1u) == P2_BLOCKS - 1);
    __syncthreads();
    if (!isLast) return;

    __shared__ float vld[NCLS];
    __shared__ float sreg[NCLS];
    __shared__ float spair[NCLS*NCLS];
    if (t < NCLS) {
        vld[t] = (g_cnt[t] > 100) ? 1.f : 0.f;   // MAX_VIEWS = 100, strict >
        float s = 0.f;
        #pragma unroll 16
        for (int d = 0; d < DD; d++) { float m = ms[t*129 + d]; s = fmaf(m, m, s); }
        sreg[t] = (s > 0.f) ? sqrtf(s) : 0.f;
    }
    for (int idx = t; idx < NCLS*NCLS; idx += P2_THREADS) {
        int a = idx / NCLS, b2 = idx % NCLS;
        float s = 0.f;
        #pragma unroll 16
        for (int d = 0; d < DD; d++) {
            float diff = ms[a*129 + d] - ms[b2*129 + d];
            s = fmaf(diff, diff, s);
        }
        float pdn = (s > 0.f) ? sqrtf(s) : 0.f;
        float hd  = fmaxf(2.f*1.5f - pdn, 0.f);   // 2*DELTA_D
        spair[idx] = hd*hd;
    }
    __syncthreads();
    if (t == 0) {
        int last = -1;
        for (int c = 0; c < NCLS; c++) if (vld[c] > 0.f) last = c;
        float tc = 0.f, lvar = 0.f, lreg = 0.f, ldist = 0.f;
        for (int c = 0; c < NCLS; c++) {
            if (vld[c] > 0.f) {
                tc   += 1.f;
                lvar += g_var[c] / fmaxf((float)g_cnt[c], 1.f);
                lreg += sreg[c];
            }
        }
        // faithful buggy double loop: a over all valid, b over valid except
        // the LAST valid class id; includes a == b pairs.
        for (int a = 0; a < NCLS; a++)
            for (int b2 = 0; b2 < NCLS; b2++)
                if (vld[a] > 0.f && vld[b2] > 0.f && b2 != last)
                    ldist += spair[a*NCLS + b2];
        out[0] = lvar/tc + ldist/(tc*(tc - 1.f)) + 0.001f*lreg/tc;  // ALPHA=BETA=1, GAMMA=1e-3
        // reset for next replay
        for (int c = 0; c < NCLS; c++) g_var[c] = 0.f;
        g_done2 = 0u;
    }
}

// ---------------------------------------------------------------- launch
extern "C" void kernel_launch(void* const* d_in, const int* in_sizes, int n_in,
                              void* d_out, int out_size) {
    const float* feats  = (const float*)d_in[0];
    const int*   labels = (const int*)d_in[1];
    float* out = (float*)d_out;

    k_prep  <<<PREP_BLOCKS, PREP_THREADS>>>(labels);
    k_pass1 <<<dim3(P1_JQ, BB, P1_SPLIT), P1_THREADS>>>(feats);
    k_pass2a<<<P2_BLOCKS, P2_THREADS>>>(feats);
    k_pass2b<<<P2_BLOCKS, P2_THREADS>>>(feats, out);
}

// round 6
// speedup vs baseline: 1.1149x; 1.1149x over previous
#include <cuda_runtime.h>
#include <math.h>

#define NCLS 19
#define DD   128
#define HWP  65536          // H*W
#define BB   8
#define NPIX (BB*HWP)       // 524288
#define NQ   (NPIX/4)       // 131072 pixel-quads

#define PREP_THREADS 256
#define PREP_HALF_BLOCKS 256        // per half-launch; 512 hist rows total
#define HIST_ROWS 512

#define P1_JP      64               // d-pair index count
#define P1_SPLIT   4
#define P1_THREADS 128
#define P1_BLOCKS  (P1_JP*BB*P1_SPLIT)   // 2048

#define P2_THREADS 256
#define P2_QPB     128              // quads per block (d-split pairs)
#define P2_BLOCKS  (NQ/P2_QPB)      // 1024

// ---- static scratch (no allocations allowed; zero-init at load) ----
__device__ float          g_sums[NCLS*DD];
__device__ float          g_means[NCLS*DD];
__device__ int            g_hist[HIST_ROWS*NCLS];
__device__ int            g_cnt[NCLS];
__device__ float          g_var[NCLS];
__device__ unsigned int   g_done1;
__device__ unsigned int   g_done2;
__device__ unsigned char  g_labs[NPIX];

// ------------------------------------------------------ label pack + hist
// 4 labels/thread via int4; one hist row per block.
__global__ void __launch_bounds__(PREP_THREADS) k_prep(const int* __restrict__ labels,
                                                       int qoff, int roff) {
    __shared__ int hist[NCLS];
    int t = threadIdx.x;
    if (t < NCLS) hist[t] = 0;
    __syncthreads();
    int q = qoff + blockIdx.x*PREP_THREADS + t;
    int4 lv = ((const int4*)labels)[q];
    uchar4 u;
    u.x = (lv.x >= 0 && lv.x < NCLS) ? (unsigned char)lv.x : (unsigned char)255;
    u.y = (lv.y >= 0 && lv.y < NCLS) ? (unsigned char)lv.y : (unsigned char)255;
    u.z = (lv.z >= 0 && lv.z < NCLS) ? (unsigned char)lv.z : (unsigned char)255;
    u.w = (lv.w >= 0 && lv.w < NCLS) ? (unsigned char)lv.w : (unsigned char)255;
    ((uchar4*)g_labs)[q] = u;
    if (u.x < NCLS) atomicAdd(&hist[u.x], 1);
    if (u.y < NCLS) atomicAdd(&hist[u.y], 1);
    if (u.z < NCLS) atomicAdd(&hist[u.z], 1);
    if (u.w < NCLS) atomicAdd(&hist[u.w], 1);
    __syncthreads();
    if (t < NCLS) g_hist[(roff + blockIdx.x)*NCLS + t] = hist[t];
}

// ------------------------------------------------------ hist -> cnt
__global__ void __launch_bounds__(256) k_cnt() {
    __shared__ int scnt[NCLS];
    int t = threadIdx.x;
    if (t < NCLS) scnt[t] = 0;
    __syncthreads();
    int loc[NCLS];
    #pragma unroll
    for (int c = 0; c < NCLS; c++) loc[c] = 0;
    const int R = HIST_ROWS / 256;           // 2
    const int* rows = &g_hist[t * R * NCLS];
    for (int r = 0; r < R; r++)
        #pragma unroll
        for (int c = 0; c < NCLS; c++) loc[c] += rows[r*NCLS + c];
    #pragma unroll
    for (int c = 0; c < NCLS; c++) atomicAdd(&scnt[c], loc[c]);
    __syncthreads();
    if (t < NCLS) g_cnt[t] = scnt[t];
}

// ---------------------------------------------------------------- pass 1
// Each thread owns a fixed d-pair (d0, d0+1): 19 packed f32x2 register
// accumulators (38 regs) -> ~28 warps/SM. One setp guards one packed add.
// Last-arriving block computes g_means and resets g_sums.
__device__ __forceinline__ unsigned long long packf2(float lo, float hi) {
    unsigned long long v;
    asm("mov.b64 %0, {%1, %2};" : "=l"(v) : "f"(lo), "f"(hi));
    return v;
}

template<int CI>
__device__ __forceinline__ void step_all(unsigned long long* acc, unsigned long long v, int lab) {
    asm("{\n\t.reg .pred p;\n\t"
        "setp.eq.s32 p, %1, %2;\n\t"
        "@p add.rn.f32x2 %0, %0, %3;\n\t}"
        : "+l"(acc[CI]) : "r"(lab), "n"(CI), "l"(v));
    if constexpr (CI + 1 < NCLS) step_all<CI+1>(acc, v, lab);
}

__global__ void __launch_bounds__(P1_THREADS) k_pass1(const float* __restrict__ feats) {
    int jp = blockIdx.x;            // d-pair index 0..63
    int b  = blockIdx.y;            // batch plane 0..7
    int s  = blockIdx.z;            // pixel split 0..3
    int d0 = jp * 2;
    const int nvec  = HWP / 4;          // 16384 float4 per plane
    const int chunk = nvec / P1_SPLIT;  // 4096
    const int base  = s * chunk;

    const float4* f0 = (const float4*)(feats + ((size_t)b*DD + d0    ) * HWP) + base;
    const float4* f1 = (const float4*)(feats + ((size_t)b*DD + d0 + 1) * HWP) + base;
    const uchar4* lb = (const uchar4*)(g_labs + (size_t)b*HWP) + base;

    unsigned long long acc[NCLS];
    #pragma unroll
    for (int c = 0; c < NCLS; c++) acc[c] = 0ull;

    for (int i = threadIdx.x; i < chunk; i += P1_THREADS) {
        float4 a0 = f0[i];
        float4 a1 = f1[i];
        uchar4 l  = lb[i];
        step_all<0>(acc, packf2(a0.x, a1.x), (int)l.x);
        step_all<0>(acc, packf2(a0.y, a1.y), (int)l.y);
        step_all<0>(acc, packf2(a0.z, a1.z), (int)l.z);
        step_all<0>(acc, packf2(a0.w, a1.w), (int)l.w);
    }

    // block reduce: warp shuffle -> shared -> global atomics
    __shared__ float shred[NCLS*2];
    if (threadIdx.x < NCLS*2) shred[threadIdx.x] = 0.f;
    __syncthreads();
    int lane = threadIdx.x & 31;
    #pragma unroll
    for (int c = 0; c < NCLS; c++) {
        float x0, x1;
        asm("mov.b64 {%0, %1}, %2;" : "=f"(x0), "=f"(x1) : "l"(acc[c]));
        #pragma unroll
        for (int o = 16; o; o >>= 1) {
            x0 += __shfl_down_sync(0xffffffffu, x0, o);
            x1 += __shfl_down_sync(0xffffffffu, x1, o);
        }
        if (lane == 0) {
            atomicAdd(&shred[c*2+0], x0);
            atomicAdd(&shred[c*2+1], x1);
        }
    }
    __syncthreads();
    if (threadIdx.x < NCLS*2) {
        int c = threadIdx.x >> 1, k = threadIdx.x & 1;
        atomicAdd(&g_sums[c*DD + d0 + k], shred[threadIdx.x]);
    }

    // ---- last-arriving block: means + scratch reset ----
    __threadfence();
    __shared__ bool isLast;
    if (threadIdx.x == 0) isLast = (atomicAdd(&g_done1, 1u) == P1_BLOCKS - 1);
    __syncthreads();
    if (!isLast) return;

    for (int idx = threadIdx.x; idx < NCLS*DD; idx += P1_THREADS) {
        int c = idx >> 7;
        g_means[idx] = g_sums[idx] / fmaxf((float)g_cnt[c], 1.f);
        g_sums[idx] = 0.f;                       // reset for next replay
    }
    if (threadIdx.x == 0) g_done1 = 0u;
}

// ---------------------------------------------------------------- pass 2
// Thread pairs split the d-range of each pixel-quad: t in [0,128) does dims
// [0,64), t+128 does [64,128); shared combine before sqrt/hinge. float4
// (LDG.128) loads kept; grid 1024 blocks -> ~40 warps/SM.
// Last-arriving block assembles the final loss.
__global__ void __launch_bounds__(P2_THREADS) k_pass2(const float* __restrict__ feats,
                                                      float* __restrict__ out) {
    __shared__ float ms[NCLS*129];
    __shared__ float vs[NCLS];
    __shared__ float ps[4*P2_QPB];
    int t = threadIdx.x;
    for (int i = t; i < NCLS*DD; i += P2_THREADS)
        ms[(i >> 7)*129 + (i & 127)] = g_means[i];
    if (t < NCLS) vs[t] = 0.f;
    __syncthreads();

    int qloc = t & (P2_QPB-1);
    int dh   = t >> 7;                     // 0 or 1
    int q    = blockIdx.x*P2_QPB + qloc;
    int b    = q >> 14;                    // 16384 quads per batch plane
    int hq   = q & 16383;
    const float4* fp = (const float4*)(feats + (size_t)b*DD*HWP + (size_t)dh*64*HWP) + hq;
    uchar4 l = ((const uchar4*)g_labs)[q];

    int l0 = l.x, l1 = l.y, l2 = l.z, l3 = l.w;
    int doff = dh*64;
    const float* m0 = ms + (l0 < NCLS ? l0 : 0)*129 + doff;
    const float* m1 = ms + (l1 < NCLS ? l1 : 0)*129 + doff;
    const float* m2 = ms + (l2 < NCLS ? l2 : 0)*129 + doff;
    const float* m3 = ms + (l3 < NCLS ? l3 : 0)*129 + doff;

    float acc0 = 0.f, acc1 = 0.f, acc2 = 0.f, acc3 = 0.f;
    #pragma unroll 8
    for (int d = 0; d < 64; d++) {
        float4 v = fp[(size_t)d * (HWP/4)];
        float df;
        df = v.x - m0[d]; acc0 = fmaf(df, df, acc0);
        df = v.y - m1[d]; acc1 = fmaf(df, df, acc1);
        df = v.z - m2[d]; acc2 = fmaf(df, df, acc2);
        df = v.w - m3[d]; acc3 = fmaf(df, df, acc3);
    }
    if (dh == 1) {
        ps[0*P2_QPB + qloc] = acc0;
        ps[1*P2_QPB + qloc] = acc1;
        ps[2*P2_QPB + qloc] = acc2;
        ps[3*P2_QPB + qloc] = acc3;
    }
    __syncthreads();
    if (dh == 0) {
        acc0 += ps[0*P2_QPB + qloc];
        acc1 += ps[1*P2_QPB + qloc];
        acc2 += ps[2*P2_QPB + qloc];
        acc3 += ps[3*P2_QPB + qloc];
        if (l0 < NCLS) { float h = fmaxf(sqrtf(acc0) - 0.5f, 0.f); atomicAdd(&vs[l0], h*h); }
        if (l1 < NCLS) { float h = fmaxf(sqrtf(acc1) - 0.5f, 0.f); atomicAdd(&vs[l1], h*h); }
        if (l2 < NCLS) { float h = fmaxf(sqrtf(acc2) - 0.5f, 0.f); atomicAdd(&vs[l2], h*h); }
        if (l3 < NCLS) { float h = fmaxf(sqrtf(acc3) - 0.5f, 0.f); atomicAdd(&vs[l3], h*h); }
    }
    __syncthreads();
    if (t < NCLS) atomicAdd(&g_var[t], vs[t]);

    // ---- last-arriving block: final loss assembly ----
    __threadfence();
    __shared__ bool isLast;
    if (t == 0) isLast = (atomicAdd(&g_done2, 1u) == P2_BLOCKS - 1);
    __syncthreads();
    if (!isLast) return;

    __shared__ float vld[NCLS];
    __shared__ float sreg[NCLS];
    __shared__ float spair[NCLS*NCLS];
    if (t < NCLS) {
        vld[t] = (g_cnt[t] > 100) ? 1.f : 0.f;   // MAX_VIEWS = 100, strict >
        float s = 0.f;
        #pragma unroll 16
        for (int d = 0; d < DD; d++) { float m = ms[t*129 + d]; s = fmaf(m, m, s); }
        sreg[t] = (s > 0.f) ? sqrtf(s) : 0.f;
    }
    for (int idx = t; idx < NCLS*NCLS; idx += P2_THREADS) {
        int a = idx / NCLS, b2 = idx % NCLS;
        float s = 0.f;
        #pragma unroll 16
        for (int d = 0; d < DD; d++) {
            float diff = ms[a*129 + d] - ms[b2*129 + d];
            s = fmaf(diff, diff, s);
        }
        float pdn = (s > 0.f) ? sqrtf(s) : 0.f;
        float hd  = fmaxf(2.f*1.5f - pdn, 0.f);   // 2*DELTA_D
        spair[idx] = hd*hd;
    }
    __syncthreads();
    if (t == 0) {
        int last = -1;
        for (int c = 0; c < NCLS; c++) if (vld[c] > 0.f) last = c;
        float tc = 0.f, lvar = 0.f, lreg = 0.f, ldist = 0.f;
        for (int c = 0; c < NCLS; c++) {
            if (vld[c] > 0.f) {
                tc   += 1.f;
                lvar += g_var[c] / fmaxf((float)g_cnt[c], 1.f);
                lreg += sreg[c];
            }
        }
        // faithful buggy double loop: a over all valid, b over valid except
        // the LAST valid class id; includes a == b pairs.
        for (int a = 0; a < NCLS; a++)
            for (int b2 = 0; b2 < NCLS; b2++)
                if (vld[a] > 0.f && vld[b2] > 0.f && b2 != last)
                    ldist += spair[a*NCLS + b2];
        out[0] = lvar/tc + ldist/(tc*(tc - 1.f)) + 0.001f*lreg/tc;  // ALPHA=BETA=1, GAMMA=1e-3
        // reset for next replay
        for (int c = 0; c < NCLS; c++) g_var[c] = 0.f;
        g_done2 = 0u;
    }
}

// ---------------------------------------------------------------- launch
// Launch index 3 (the one ncu captures) = k_pass1.
extern "C" void kernel_launch(void* const* d_in, const int* in_sizes, int n_in,
                              void* d_out, int out_size) {
    const float* feats  = (const float*)d_in[0];
    const int*   labels = (const int*)d_in[1];
    float* out = (float*)d_out;

    k_prep <<<PREP_HALF_BLOCKS, PREP_THREADS>>>(labels, 0,    0);                 // idx 0
    k_prep <<<PREP_HALF_BLOCKS, PREP_THREADS>>>(labels, NQ/2, PREP_HALF_BLOCKS);  // idx 1
    k_cnt  <<<1, 256>>>();                                                        // idx 2
    k_pass1<<<dim3(P1_JP, BB, P1_SPLIT), P1_THREADS>>>(feats);                    // idx 3 (profiled)
    k_pass2<<<P2_BLOCKS, P2_THREADS>>>(feats, out);                               // idx 4
}

// round 7
// speedup vs baseline: 2.0396x; 1.8294x over previous
#include <cuda_runtime.h>
#include <math.h>

#define NCLS 19
#define DD   128
#define HWP  65536          // H*W
#define BB   8
#define NPIX (BB*HWP)       // 524288
#define NQ   (NPIX/4)       // 131072 pixel-quads

#define PREP_THREADS 256
#define PREP_BLOCKS  512
#define HIST_ROWS    512

#define P1_BLOCKS  512
#define P1_THREADS 256              // 8 warps; warp w owns dims [16w,16w+16)
#define P1_PX      (NPIX/P1_BLOCKS) // 1024 pixels per block
#define P1_KSTEPS  (P1_PX/16)       // 64

#define P2_THREADS 256
#define P2_QPB     128              // quads per block (d-split pairs)
#define P2_BLOCKS  (NQ/P2_QPB)      // 1024

// ---- static scratch (no allocations allowed; zero-init at load) ----
__device__ float          g_sums[NCLS*DD];
__device__ float          g_means[NCLS*DD];
__device__ int            g_hist[HIST_ROWS*NCLS];
__device__ int            g_cnt[NCLS];
__device__ float          g_var[NCLS];
__device__ unsigned int   g_done1;
__device__ unsigned int   g_done2;
__device__ unsigned char  g_labs[NPIX];

// ------------------------------------------------------ label pack + hist
__global__ void __launch_bounds__(PREP_THREADS) k_prep(const int* __restrict__ labels) {
    __shared__ int hist[NCLS];
    int t = threadIdx.x;
    if (t < NCLS) hist[t] = 0;
    __syncthreads();
    int q = blockIdx.x*PREP_THREADS + t;
    int4 lv = ((const int4*)labels)[q];
    uchar4 u;
    u.x = (lv.x >= 0 && lv.x < NCLS) ? (unsigned char)lv.x : (unsigned char)255;
    u.y = (lv.y >= 0 && lv.y < NCLS) ? (unsigned char)lv.y : (unsigned char)255;
    u.z = (lv.z >= 0 && lv.z < NCLS) ? (unsigned char)lv.z : (unsigned char)255;
    u.w = (lv.w >= 0 && lv.w < NCLS) ? (unsigned char)lv.w : (unsigned char)255;
    ((uchar4*)g_labs)[q] = u;
    if (u.x < NCLS) atomicAdd(&hist[u.x], 1);
    if (u.y < NCLS) atomicAdd(&hist[u.y], 1);
    if (u.z < NCLS) atomicAdd(&hist[u.z], 1);
    if (u.w < NCLS) atomicAdd(&hist[u.w], 1);
    __syncthreads();
    if (t < NCLS) g_hist[blockIdx.x*NCLS + t] = hist[t];
}

// ------------------------------------------------------ hist -> cnt
__global__ void __launch_bounds__(256) k_cnt() {
    __shared__ int scnt[NCLS];
    int t = threadIdx.x;
    if (t < NCLS) scnt[t] = 0;
    __syncthreads();
    int loc[NCLS];
    #pragma unroll
    for (int c = 0; c < NCLS; c++) loc[c] = 0;
    const int R = HIST_ROWS / 256;           // 2
    const int* rows = &g_hist[t * R * NCLS];
    for (int r = 0; r < R; r++)
        #pragma unroll
        for (int c = 0; c < NCLS; c++) loc[c] += rows[r*NCLS + c];
    #pragma unroll
    for (int c = 0; c < NCLS; c++) atomicAdd(&scnt[c], loc[c]);
    __syncthreads();
    if (t < NCLS) g_cnt[t] = scnt[t];
}

// ---------------------------------------------------------------- pass 1
// Segment-sum as GEMM: D[d][c] = sum_p feats[d][p] * onehot(lab[p]==c).
// Per warp: mma.sync.m16n8k16, A = feats [16 dims x 16 px] bf16 loaded
// straight from global in fragment layout, B = onehot built in registers,
// C = fp32 [16 d x 24 cls] accumulated across 64 k-steps. Last-arriving
// block computes g_means and resets g_sums.
__global__ void __launch_bounds__(P1_THREADS) k_pass1(const float* __restrict__ feats) {
    int w    = threadIdx.x >> 5;
    int lane = threadIdx.x & 31;
    int gid  = lane >> 2;            // 0..7
    int ktid = lane & 3;             // 0..3
    int pxg  = blockIdx.x * P1_PX;   // global pixel base (plane-aligned: 1024 | 65536)
    int b    = pxg >> 16;
    int po   = pxg & 65535;

    int d_lo = w*16 + gid;
    const float* rowA = feats + ((size_t)b*DD + d_lo    ) * HWP + po;  // A[gid]
    const float* rowB = feats + ((size_t)b*DD + d_lo + 8) * HWP + po;  // A[gid+8]
    const unsigned char* labp = g_labs + pxg;

    float c0[4] = {0.f,0.f,0.f,0.f};
    float c1[4] = {0.f,0.f,0.f,0.f};
    float c2[4] = {0.f,0.f,0.f,0.f};

    #pragma unroll 2
    for (int ks = 0; ks < P1_KSTEPS; ks++) {
        int p0 = ks*16 + 2*ktid;     // thread's k-anchor within the 16-px tile
        float2 fa0 = *(const float2*)(rowA + p0);        // A[gid][k0,k0+1]
        float2 fa1 = *(const float2*)(rowB + p0);        // A[gid+8][k0,k0+1]
        float2 fa2 = *(const float2*)(rowA + p0 + 8);    // A[gid][k0+8,k0+9]
        float2 fa3 = *(const float2*)(rowB + p0 + 8);    // A[gid+8][k0+8,k0+9]
        unsigned a0, a1, a2, a3;
        asm("cvt.rn.bf16x2.f32 %0, %1, %2;" : "=r"(a0) : "f"(fa0.y), "f"(fa0.x));
        asm("cvt.rn.bf16x2.f32 %0, %1, %2;" : "=r"(a1) : "f"(fa1.y), "f"(fa1.x));
        asm("cvt.rn.bf16x2.f32 %0, %1, %2;" : "=r"(a2) : "f"(fa2.y), "f"(fa2.x));
        asm("cvt.rn.bf16x2.f32 %0, %1, %2;" : "=r"(a3) : "f"(fa3.y), "f"(fa3.x));

        unsigned short L01 = *(const unsigned short*)(labp + p0);      // L1-resident
        unsigned short L89 = *(const unsigned short*)(labp + p0 + 8);
        int l0 = L01 & 0xFF, l1 = L01 >> 8;
        int l8 = L89 & 0xFF, l9 = L89 >> 8;

        // tile t covers classes [8t, 8t+8); this thread's B column n = gid
        {   int cls = gid;
            unsigned b0 = (l0==cls ? 0x3F80u : 0u) | (l1==cls ? 0x3F800000u : 0u);
            unsigned b1 = (l8==cls ? 0x3F80u : 0u) | (l9==cls ? 0x3F800000u : 0u);
            asm("mma.sync.aligned.m16n8k16.row.col.f32.bf16.bf16.f32 "
                "{%0,%1,%2,%3}, {%4,%5,%6,%7}, {%8,%9}, {%0,%1,%2,%3};"
                : "+f"(c0[0]), "+f"(c0[1]), "+f"(c0[2]), "+f"(c0[3])
                : "r"(a0), "r"(a1), "r"(a2), "r"(a3), "r"(b0), "r"(b1));
        }
        {   int cls = gid + 8;
            unsigned b0 = (l0==cls ? 0x3F80u : 0u) | (l1==cls ? 0x3F800000u : 0u);
            unsigned b1 = (l8==cls ? 0x3F80u : 0u) | (l9==cls ? 0x3F800000u : 0u);
            asm("mma.sync.aligned.m16n8k16.row.col.f32.bf16.bf16.f32 "
                "{%0,%1,%2,%3}, {%4,%5,%6,%7}, {%8,%9}, {%0,%1,%2,%3};"
                : "+f"(c1[0]), "+f"(c1[1]), "+f"(c1[2]), "+f"(c1[3])
                : "r"(a0), "r"(a1), "r"(a2), "r"(a3), "r"(b0), "r"(b1));
        }
        {   int cls = gid + 16;
            unsigned b0 = (l0==cls ? 0x3F80u : 0u) | (l1==cls ? 0x3F800000u : 0u);
            unsigned b1 = (l8==cls ? 0x3F80u : 0u) | (l9==cls ? 0x3F800000u : 0u);
            asm("mma.sync.aligned.m16n8k16.row.col.f32.bf16.bf16.f32 "
                "{%0,%1,%2,%3}, {%4,%5,%6,%7}, {%8,%9}, {%0,%1,%2,%3};"
                : "+f"(c2[0]), "+f"(c2[1]), "+f"(c2[2]), "+f"(c2[3])
                : "r"(a0), "r"(a1), "r"(a2), "r"(a3), "r"(b0), "r"(b1));
        }
    }

    // writeout: C[m][n] -> d = w*16 + m (m = gid, gid+8), cls = 8t + n (n = 2ktid,2ktid+1)
    int dA = w*16 + gid, dB = dA + 8;
    {   int n0 = 2*ktid, n1 = n0 + 1;             // tile 0: cls 0..7
        atomicAdd(&g_sums[n0*DD + dA], c0[0]);
        atomicAdd(&g_sums[n1*DD + dA], c0[1]);
        atomicAdd(&g_sums[n0*DD + dB], c0[2]);
        atomicAdd(&g_sums[n1*DD + dB], c0[3]);
    }
    {   int n0 = 8 + 2*ktid, n1 = n0 + 1;         // tile 1: cls 8..15
        atomicAdd(&g_sums[n0*DD + dA], c1[0]);
        atomicAdd(&g_sums[n1*DD + dA], c1[1]);
        atomicAdd(&g_sums[n0*DD + dB], c1[2]);
        atomicAdd(&g_sums[n1*DD + dB], c1[3]);
    }
    {   int n0 = 16 + 2*ktid, n1 = n0 + 1;        // tile 2: cls 16..23 (keep <19)
        if (n0 < NCLS) { atomicAdd(&g_sums[n0*DD + dA], c2[0]);
                         atomicAdd(&g_sums[n0*DD + dB], c2[2]); }
        if (n1 < NCLS) { atomicAdd(&g_sums[n1*DD + dA], c2[1]);
                         atomicAdd(&g_sums[n1*DD + dB], c2[3]); }
    }

    // ---- last-arriving block: means + scratch reset ----
    __threadfence();
    __shared__ bool isLast;
    if (threadIdx.x == 0) isLast = (atomicAdd(&g_done1, 1u) == P1_BLOCKS - 1);
    __syncthreads();
    if (!isLast) return;

    for (int idx = threadIdx.x; idx < NCLS*DD; idx += P1_THREADS) {
        int c = idx >> 7;
        g_means[idx] = g_sums[idx] / fmaxf((float)g_cnt[c], 1.f);
        g_sums[idx] = 0.f;                       // reset for next replay
    }
    if (threadIdx.x == 0) g_done1 = 0u;
}

// ---------------------------------------------------------------- pass 2
// Thread pairs split the d-range of each pixel-quad: t in [0,128) does dims
// [0,64), t+128 does [64,128); shared combine before sqrt/hinge.
// Last-arriving block assembles the final loss.
__global__ void __launch_bounds__(P2_THREADS) k_pass2(const float* __restrict__ feats,
                                                      float* __restrict__ out) {
    __shared__ float ms[NCLS*129];
    __shared__ float vs[NCLS];
    __shared__ float ps[4*P2_QPB];
    int t = threadIdx.x;
    for (int i = t; i < NCLS*DD; i += P2_THREADS)
        ms[(i >> 7)*129 + (i & 127)] = g_means[i];
    if (t < NCLS) vs[t] = 0.f;
    __syncthreads();

    int qloc = t & (P2_QPB-1);
    int dh   = t >> 7;                     // 0 or 1
    int q    = blockIdx.x*P2_QPB + qloc;
    int b    = q >> 14;                    // 16384 quads per batch plane
    int hq   = q & 16383;
    const float4* fp = (const float4*)(feats + (size_t)b*DD*HWP + (size_t)dh*64*HWP) + hq;
    uchar4 l = ((const uchar4*)g_labs)[q];

    int l0 = l.x, l1 = l.y, l2 = l.z, l3 = l.w;
    int doff = dh*64;
    const float* m0 = ms + (l0 < NCLS ? l0 : 0)*129 + doff;
    const float* m1 = ms + (l1 < NCLS ? l1 : 0)*129 + doff;
    const float* m2 = ms + (l2 < NCLS ? l2 : 0)*129 + doff;
    const float* m3 = ms + (l3 < NCLS ? l3 : 0)*129 + doff;

    float acc0 = 0.f, acc1 = 0.f, acc2 = 0.f, acc3 = 0.f;
    #pragma unroll 8
    for (int d = 0; d < 64; d++) {
        float4 v = fp[(size_t)d * (HWP/4)];
        float df;
        df = v.x - m0[d]; acc0 = fmaf(df, df, acc0);
        df = v.y - m1[d]; acc1 = fmaf(df, df, acc1);
        df = v.z - m2[d]; acc2 = fmaf(df, df, acc2);
        df = v.w - m3[d]; acc3 = fmaf(df, df, acc3);
    }
    if (dh == 1) {
        ps[0*P2_QPB + qloc] = acc0;
        ps[1*P2_QPB + qloc] = acc1;
        ps[2*P2_QPB + qloc] = acc2;
        ps[3*P2_QPB + qloc] = acc3;
    }
    __syncthreads();
    if (dh == 0) {
        acc0 += ps[0*P2_QPB + qloc];
        acc1 += ps[1*P2_QPB + qloc];
        acc2 += ps[2*P2_QPB + qloc];
        acc3 += ps[3*P2_QPB + qloc];
        if (l0 < NCLS) { float h = fmaxf(sqrtf(acc0) - 0.5f, 0.f); atomicAdd(&vs[l0], h*h); }
        if (l1 < NCLS) { float h = fmaxf(sqrtf(acc1) - 0.5f, 0.f); atomicAdd(&vs[l1], h*h); }
        if (l2 < NCLS) { float h = fmaxf(sqrtf(acc2) - 0.5f, 0.f); atomicAdd(&vs[l2], h*h); }
        if (l3 < NCLS) { float h = fmaxf(sqrtf(acc3) - 0.5f, 0.f); atomicAdd(&vs[l3], h*h); }
    }
    __syncthreads();
    if (t < NCLS) atomicAdd(&g_var[t], vs[t]);

    // ---- last-arriving block: final loss assembly ----
    __threadfence();
    __shared__ bool isLast;
    if (t == 0) isLast = (atomicAdd(&g_done2, 1u) == P2_BLOCKS - 1);
    __syncthreads();
    if (!isLast) return;

    __shared__ float vld[NCLS];
    __shared__ float sreg[NCLS];
    __shared__ float spair[NCLS*NCLS];
    if (t < NCLS) {
        vld[t] = (g_cnt[t] > 100) ? 1.f : 0.f;   // MAX_VIEWS = 100, strict >
        float s = 0.f;
        #pragma unroll 16
        for (int d = 0; d < DD; d++) { float m = ms[t*129 + d]; s = fmaf(m, m, s); }
        sreg[t] = (s > 0.f) ? sqrtf(s) : 0.f;
    }
    for (int idx = t; idx < NCLS*NCLS; idx += P2_THREADS) {
        int a = idx / NCLS, b2 = idx % NCLS;
        float s = 0.f;
        #pragma unroll 16
        for (int d = 0; d < DD; d++) {
            float diff = ms[a*129 + d] - ms[b2*129 + d];
            s = fmaf(diff, diff, s);
        }
        float pdn = (s > 0.f) ? sqrtf(s) : 0.f;
        float hd  = fmaxf(2.f*1.5f - pdn, 0.f);   // 2*DELTA_D
        spair[idx] = hd*hd;
    }
    __syncthreads();
    if (t == 0) {
        int last = -1;
        for (int c = 0; c < NCLS; c++) if (vld[c] > 0.f) last = c;
        float tc = 0.f, lvar = 0.f, lreg = 0.f, ldist = 0.f;
        for (int c = 0; c < NCLS; c++) {
            if (vld[c] > 0.f) {
                tc   += 1.f;
                lvar += g_var[c] / fmaxf((float)g_cnt[c], 1.f);
                lreg += sreg[c];
            }
        }
        // faithful buggy double loop: a over all valid, b over valid except
        // the LAST valid class id; includes a == b pairs.
        for (int a = 0; a < NCLS; a++)
            for (int b2 = 0; b2 < NCLS; b2++)
                if (vld[a] > 0.f && vld[b2] > 0.f && b2 != last)
                    ldist += spair[a*NCLS + b2];
        out[0] = lvar/tc + ldist/(tc*(tc - 1.f)) + 0.001f*lreg/tc;  // ALPHA=BETA=1, GAMMA=1e-3
        // reset for next replay
        for (int c = 0; c < NCLS; c++) g_var[c] = 0.f;
        g_done2 = 0u;
    }
}

// ---------------------------------------------------------------- launch
// Launch index 3 (the one ncu captures) = k_pass2.
extern "C" void kernel_launch(void* const* d_in, const int* in_sizes, int n_in,
                              void* d_out, int out_size) {
    const float* feats  = (const float*)d_in[0];
    const int*   labels = (const int*)d_in[1];
    float* out = (float*)d_out;

    k_prep <<<PREP_BLOCKS, PREP_THREADS>>>(labels);      // idx 0
    k_cnt  <<<1, 256>>>();                               // idx 1
    k_pass1<<<P1_BLOCKS, P1_THREADS>>>(feats);           // idx 2
    k_pass2<<<P2_BLOCKS, P2_THREADS>>>(feats, out);      // idx 3 (profiled)
}

// round 8
// speedup vs baseline: 2.3238x; 1.1393x over previous
#include <cuda_runtime.h>
#include <math.h>

#define NCLS 19
#define DD   128
#define HWP  65536          // H*W
#define BB   8
#define NPIX (BB*HWP)       // 524288
#define NQ   (NPIX/4)       // 131072 pixel-quads

#define PREP_THREADS 256
#define PREP_HALF    256            // blocks per half-launch
#define HIST_ROWS    512

#define P1_BLOCKS  444              // 3 x 148 SMs, single wave
#define P1_THREADS 256              // 8 warps; warp w owns dims [16w,16w+16)
#define P1_CHUNK   256              // pixels per chunk (16 ksteps)
#define P1_NCHUNK  (NPIX/P1_CHUNK)  // 2048

#define P2_THREADS 256
#define P2_QPB     128              // quads per block (d-split pairs)
#define P2_BLOCKS  (NQ/P2_QPB)      // 1024

// ---- static scratch (no allocations allowed; zero-init at load) ----
__device__ float          g_sums[NCLS*DD];
__device__ int            g_hist[HIST_ROWS*NCLS];
__device__ int            g_cnt[NCLS];
__device__ float          g_var[NCLS];
__device__ unsigned int   g_done2;
__device__ unsigned char  g_labs[NPIX];

// ------------------------------------------------------ label pack + hist
__global__ void __launch_bounds__(PREP_THREADS) k_prep(const int* __restrict__ labels,
                                                       int qoff, int roff) {
    __shared__ int hist[NCLS];
    int t = threadIdx.x;
    if (t < NCLS) hist[t] = 0;
    __syncthreads();
    int q = qoff + blockIdx.x*PREP_THREADS + t;
    int4 lv = ((const int4*)labels)[q];
    uchar4 u;
    u.x = (lv.x >= 0 && lv.x < NCLS) ? (unsigned char)lv.x : (unsigned char)255;
    u.y = (lv.y >= 0 && lv.y < NCLS) ? (unsigned char)lv.y : (unsigned char)255;
    u.z = (lv.z >= 0 && lv.z < NCLS) ? (unsigned char)lv.z : (unsigned char)255;
    u.w = (lv.w >= 0 && lv.w < NCLS) ? (unsigned char)lv.w : (unsigned char)255;
    ((uchar4*)g_labs)[q] = u;
    if (u.x < NCLS) atomicAdd(&hist[u.x], 1);
    if (u.y < NCLS) atomicAdd(&hist[u.y], 1);
    if (u.z < NCLS) atomicAdd(&hist[u.z], 1);
    if (u.w < NCLS) atomicAdd(&hist[u.w], 1);
    __syncthreads();
    if (t < NCLS) g_hist[(roff + blockIdx.x)*NCLS + t] = hist[t];
}

// ------------------------------------------------------ hist -> cnt
__global__ void __launch_bounds__(256) k_cnt() {
    __shared__ int scnt[NCLS];
    int t = threadIdx.x;
    if (t < NCLS) scnt[t] = 0;
    __syncthreads();
    int loc[NCLS];
    #pragma unroll
    for (int c = 0; c < NCLS; c++) loc[c] = 0;
    const int R = HIST_ROWS / 256;           // 2
    const int* rows = &g_hist[t * R * NCLS];
    for (int r = 0; r < R; r++)
        #pragma unroll
        for (int c = 0; c < NCLS; c++) loc[c] += rows[r*NCLS + c];
    #pragma unroll
    for (int c = 0; c < NCLS; c++) atomicAdd(&scnt[c], loc[c]);
    __syncthreads();
    if (t < NCLS) g_cnt[t] = scnt[t];
}

// ---------------------------------------------------------------- pass 1
// Segment-sum as GEMM: D[d][c] = sum_p feats[d][p] * onehot(lab[p]==c).
// Per warp: mma.sync.m16n8k16, A = feats [16 dims x 16 px] bf16 loaded
// straight from global in fragment layout, B = onehot built in registers,
// C = fp32 [16 d x 24 cls]. Grid-stride over 2048 chunks of 256 px;
// accumulators persist across chunks; single atomic writeout.
__global__ void __launch_bounds__(P1_THREADS, 3) k_pass1(const float* __restrict__ feats) {
    int w    = threadIdx.x >> 5;
    int lane = threadIdx.x & 31;
    int gid  = lane >> 2;            // 0..7
    int ktid = lane & 3;             // 0..3
    int d_lo = w*16 + gid;

    float c0[4] = {0.f,0.f,0.f,0.f};
    float c1[4] = {0.f,0.f,0.f,0.f};
    float c2[4] = {0.f,0.f,0.f,0.f};

    for (int ch = blockIdx.x; ch < P1_NCHUNK; ch += P1_BLOCKS) {
        int pxg = ch * P1_CHUNK;         // plane-aligned: 256 | 65536
        int b   = pxg >> 16;
        int po  = pxg & 65535;
        const float* rowA = feats + ((size_t)b*DD + d_lo    ) * HWP + po;
        const float* rowB = feats + ((size_t)b*DD + d_lo + 8) * HWP + po;
        const unsigned char* labp = g_labs + pxg;

        #pragma unroll 2
        for (int ks = 0; ks < P1_CHUNK/16; ks++) {
            int p0 = ks*16 + 2*ktid;     // thread's k-anchor within the 16-px tile
            float2 fa0 = *(const float2*)(rowA + p0);        // A[gid][k0,k0+1]
            float2 fa1 = *(const float2*)(rowB + p0);        // A[gid+8][k0,k0+1]
            float2 fa2 = *(const float2*)(rowA + p0 + 8);    // A[gid][k0+8,k0+9]
            float2 fa3 = *(const float2*)(rowB + p0 + 8);    // A[gid+8][k0+8,k0+9]
            unsigned a0, a1, a2, a3;
            asm("cvt.rn.bf16x2.f32 %0, %1, %2;" : "=r"(a0) : "f"(fa0.y), "f"(fa0.x));
            asm("cvt.rn.bf16x2.f32 %0, %1, %2;" : "=r"(a1) : "f"(fa1.y), "f"(fa1.x));
            asm("cvt.rn.bf16x2.f32 %0, %1, %2;" : "=r"(a2) : "f"(fa2.y), "f"(fa2.x));
            asm("cvt.rn.bf16x2.f32 %0, %1, %2;" : "=r"(a3) : "f"(fa3.y), "f"(fa3.x));

            unsigned short L01 = *(const unsigned short*)(labp + p0);
            unsigned short L89 = *(const unsigned short*)(labp + p0 + 8);
            int l0 = L01 & 0xFF, l1 = L01 >> 8;
            int l8 = L89 & 0xFF, l9 = L89 >> 8;

            {   int cls = gid;                       // tile 0: classes 0..7
                unsigned b0 = (l0==cls ? 0x3F80u : 0u) | (l1==cls ? 0x3F800000u : 0u);
                unsigned b1 = (l8==cls ? 0x3F80u : 0u) | (l9==cls ? 0x3F800000u : 0u);
                asm("mma.sync.aligned.m16n8k16.row.col.f32.bf16.bf16.f32 "
                    "{%0,%1,%2,%3}, {%4,%5,%6,%7}, {%8,%9}, {%0,%1,%2,%3};"
                    : "+f"(c0[0]), "+f"(c0[1]), "+f"(c0[2]), "+f"(c0[3])
                    : "r"(a0), "r"(a1), "r"(a2), "r"(a3), "r"(b0), "r"(b1));
            }
            {   int cls = gid + 8;                   // tile 1: classes 8..15
                unsigned b0 = (l0==cls ? 0x3F80u : 0u) | (l1==cls ? 0x3F800000u : 0u);
                unsigned b1 = (l8==cls ? 0x3F80u : 0u) | (l9==cls ? 0x3F800000u : 0u);
                asm("mma.sync.aligned.m16n8k16.row.col.f32.bf16.bf16.f32 "
                    "{%0,%1,%2,%3}, {%4,%5,%6,%7}, {%8,%9}, {%0,%1,%2,%3};"
                    : "+f"(c1[0]), "+f"(c1[1]), "+f"(c1[2]), "+f"(c1[3])
                    : "r"(a0), "r"(a1), "r"(a2), "r"(a3), "r"(b0), "r"(b1));
            }
            {   int cls = gid + 16;                  // tile 2: classes 16..23
                unsigned b0 = (l0==cls ? 0x3F80u : 0u) | (l1==cls ? 0x3F800000u : 0u);
                unsigned b1 = (l8==cls ? 0x3F80u : 0u) | (l9==cls ? 0x3F800000u : 0u);
                asm("mma.sync.aligned.m16n8k16.row.col.f32.bf16.bf16.f32 "
                    "{%0,%1,%2,%3}, {%4,%5,%6,%7}, {%8,%9}, {%0,%1,%2,%3};"
                    : "+f"(c2[0]), "+f"(c2[1]), "+f"(c2[2]), "+f"(c2[3])
                    : "r"(a0), "r"(a1), "r"(a2), "r"(a3), "r"(b0), "r"(b1));
            }
        }
    }

    // writeout: C[m][n] -> d = w*16 + m (m = gid, gid+8), cls = 8t + n
    int dA = w*16 + gid, dB = dA + 8;
    {   int n0 = 2*ktid, n1 = n0 + 1;             // tile 0: cls 0..7
        atomicAdd(&g_sums[n0*DD + dA], c0[0]);
        atomicAdd(&g_sums[n1*DD + dA], c0[1]);
        atomicAdd(&g_sums[n0*DD + dB], c0[2]);
        atomicAdd(&g_sums[n1*DD + dB], c0[3]);
    }
    {   int n0 = 8 + 2*ktid, n1 = n0 + 1;         // tile 1: cls 8..15
        atomicAdd(&g_sums[n0*DD + dA], c1[0]);
        atomicAdd(&g_sums[n1*DD + dA], c1[1]);
        atomicAdd(&g_sums[n0*DD + dB], c1[2]);
        atomicAdd(&g_sums[n1*DD + dB], c1[3]);
    }
    {   int n0 = 16 + 2*ktid, n1 = n0 + 1;        // tile 2: cls 16..23 (keep <19)
        if (n0 < NCLS) { atomicAdd(&g_sums[n0*DD + dA], c2[0]);
                         atomicAdd(&g_sums[n0*DD + dB], c2[2]); }
        if (n1 < NCLS) { atomicAdd(&g_sums[n1*DD + dA], c2[1]);
                         atomicAdd(&g_sums[n1*DD + dB], c2[3]); }
    }
}

// ---------------------------------------------------------------- pass 2
// Each block computes means from g_sums/g_cnt into shared (stride 129,
// conflict-free). Thread pairs split the d-range of each pixel-quad.
// __launch_bounds__(256,7): <=36 regs -> 7 blocks/SM -> 1024 blocks single
// wave. Last-arriving block assembles the final loss and resets scratch.
__global__ void __launch_bounds__(P2_THREADS, 7) k_pass2(const float* __restrict__ feats,
                                                         float* __restrict__ out) {
    __shared__ float ms[NCLS*129];
    __shared__ float vs[NCLS];
    __shared__ float ps[4*P2_QPB];
    int t = threadIdx.x;
    for (int i = t; i < NCLS*DD; i += P2_THREADS) {
        int c = i >> 7;
        ms[c*129 + (i & 127)] = g_sums[i] / fmaxf((float)g_cnt[c], 1.f);
    }
    if (t < NCLS) vs[t] = 0.f;
    __syncthreads();

    int qloc = t & (P2_QPB-1);
    int dh   = t >> 7;                     // 0 or 1
    int q    = blockIdx.x*P2_QPB + qloc;
    int b    = q >> 14;                    // 16384 quads per batch plane
    int hq   = q & 16383;
    const float4* fp = (const float4*)(feats + (size_t)b*DD*HWP + (size_t)dh*64*HWP) + hq;
    uchar4 l = ((const uchar4*)g_labs)[q];

    int l0 = l.x, l1 = l.y, l2 = l.z, l3 = l.w;
    int doff = dh*64;
    const float* m0 = ms + (l0 < NCLS ? l0 : 0)*129 + doff;
    const float* m1 = ms + (l1 < NCLS ? l1 : 0)*129 + doff;
    const float* m2 = ms + (l2 < NCLS ? l2 : 0)*129 + doff;
    const float* m3 = ms + (l3 < NCLS ? l3 : 0)*129 + doff;

    float acc0 = 0.f, acc1 = 0.f, acc2 = 0.f, acc3 = 0.f;
    #pragma unroll 8
    for (int d = 0; d < 64; d++) {
        float4 v = fp[(size_t)d * (HWP/4)];
        float df;
        df = v.x - m0[d]; acc0 = fmaf(df, df, acc0);
        df = v.y - m1[d]; acc1 = fmaf(df, df, acc1);
        df = v.z - m2[d]; acc2 = fmaf(df, df, acc2);
        df = v.w - m3[d]; acc3 = fmaf(df, df, acc3);
    }
    if (dh == 1) {
        ps[0*P2_QPB + qloc] = acc0;
        ps[1*P2_QPB + qloc] = acc1;
        ps[2*P2_QPB + qloc] = acc2;
        ps[3*P2_QPB + qloc] = acc3;
    }
    __syncthreads();
    if (dh == 0) {
        acc0 += ps[0*P2_QPB + qloc];
        acc1 += ps[1*P2_QPB + qloc];
        acc2 += ps[2*P2_QPB + qloc];
        acc3 += ps[3*P2_QPB + qloc];
        if (l0 < NCLS) { float h = fmaxf(sqrtf(acc0) - 0.5f, 0.f); atomicAdd(&vs[l0], h*h); }
        if (l1 < NCLS) { float h = fmaxf(sqrtf(acc1) - 0.5f, 0.f); atomicAdd(&vs[l1], h*h); }
        if (l2 < NCLS) { float h = fmaxf(sqrtf(acc2) - 0.5f, 0.f); atomicAdd(&vs[l2], h*h); }
        if (l3 < NCLS) { float h = fmaxf(sqrtf(acc3) - 0.5f, 0.f); atomicAdd(&vs[l3], h*h); }
    }
    __syncthreads();
    if (t < NCLS) atomicAdd(&g_var[t], vs[t]);

    // ---- last-arriving block: final loss assembly + scratch reset ----
    __threadfence();
    __shared__ bool isLast;
    if (t == 0) isLast = (atomicAdd(&g_done2, 1u) == P2_BLOCKS - 1);
    __syncthreads();
    if (!isLast) return;

    __shared__ float vld[NCLS];
    __shared__ float sreg[NCLS];
    __shared__ float spair[NCLS*NCLS];
    if (t < NCLS) {
        vld[t] = (g_cnt[t] > 100) ? 1.f : 0.f;   // MAX_VIEWS = 100, strict >
        float s = 0.f;
        #pragma unroll 16
        for (int d = 0; d < DD; d++) { float m = ms[t*129 + d]; s = fmaf(m, m, s); }
        sreg[t] = (s > 0.f) ? sqrtf(s) : 0.f;
    }
    for (int idx = t; idx < NCLS*NCLS; idx += P2_THREADS) {
        int a = idx / NCLS, b2 = idx % NCLS;
        float s = 0.f;
        #pragma unroll 16
        for (int d = 0; d < DD; d++) {
            float diff = ms[a*129 + d] - ms[b2*129 + d];
            s = fmaf(diff, diff, s);
        }
        float pdn = (s > 0.f) ? sqrtf(s) : 0.f;
        float hd  = fmaxf(2.f*1.5f - pdn, 0.f);   // 2*DELTA_D
        spair[idx] = hd*hd;
    }
    // reset g_sums for next replay (all pass2 reads of g_sums are done)
    for (int i = t; i < NCLS*DD; i += P2_THREADS) g_sums[i] = 0.f;
    __syncthreads();
    if (t == 0) {
        int last = -1;
        for (int c = 0; c < NCLS; c++) if (vld[c] > 0.f) last = c;
        float tc = 0.f, lvar = 0.f, lreg = 0.f, ldist = 0.f;
        for (int c = 0; c < NCLS; c++) {
            if (vld[c] > 0.f) {
                tc   += 1.f;
                lvar += g_var[c] / fmaxf((float)g_cnt[c], 1.f);
                lreg += sreg[c];
            }
        }
        // faithful buggy double loop: a over all valid, b over valid except
        // the LAST valid class id; includes a == b pairs.
        for (int a = 0; a < NCLS; a++)
            for (int b2 = 0; b2 < NCLS; b2++)
                if (vld[a] > 0.f && vld[b2] > 0.f && b2 != last)
                    ldist += spair[a*NCLS + b2];
        out[0] = lvar/tc + ldist/(tc*(tc - 1.f)) + 0.001f*lreg/tc;  // ALPHA=BETA=1, GAMMA=1e-3
        // reset for next replay
        for (int c = 0; c < NCLS; c++) g_var[c] = 0.f;
        g_done2 = 0u;
    }
}

// ---------------------------------------------------------------- launch
// Launch index 3 (the one ncu captures) = k_pass1 (MMA kernel).
extern "C" void kernel_launch(void* const* d_in, const int* in_sizes, int n_in,
                              void* d_out, int out_size) {
    const float* feats  = (const float*)d_in[0];
    const int*   labels = (const int*)d_in[1];
    float* out = (float*)d_out;

    k_prep <<<PREP_HALF, PREP_THREADS>>>(labels, 0,    0);          // idx 0
    k_prep <<<PREP_HALF, PREP_THREADS>>>(labels, NQ/2, PREP_HALF);  // idx 1
    k_cnt  <<<1, 256>>>();                                          // idx 2
    k_pass1<<<P1_BLOCKS, P1_THREADS>>>(feats);                      // idx 3 (profiled)
    k_pass2<<<P2_BLOCKS, P2_THREADS>>>(feats, out);                 // idx 4
}

// round 9
// speedup vs baseline: 2.3292x; 1.0023x over previous
#include <cuda_runtime.h>
#include <math.h>

#define NCLS 19
#define DD   128
#define HWP  65536          // H*W
#define BB   8
#define NPIX (BB*HWP)       // 524288
#define NQ   (NPIX/4)       // 131072 pixel-quads

#define PREP_THREADS 256
#define PREP_HALF    256            // blocks per half-launch
#define PREP_BLOCKS  (2*PREP_HALF)  // 512 total
#define HIST_ROWS    512

#define P1_BLOCKS  592              // 4 x 148 SMs, single wave
#define P1_THREADS 256              // 8 warps; warp w owns dims [16w,16w+16)
#define P1_CHUNK   128              // pixels per chunk (8 ksteps)
#define P1_NCHUNK  (NPIX/P1_CHUNK)  // 4096

#define P2_THREADS 256
#define P2_QPB     128              // quads per block (d-split pairs)
#define P2_BLOCKS  (NQ/P2_QPB)      // 1024

// ---- static scratch (no allocations allowed; zero-init at load) ----
__device__ float          g_sums[NCLS*DD];
__device__ int            g_hist[HIST_ROWS*NCLS];
__device__ int            g_cnt[NCLS];
__device__ float          g_var[NCLS];
__device__ unsigned int   g_done0;
__device__ unsigned int   g_done2;
__device__ unsigned char  g_labs[NPIX];

// ------------------------------------------------------ label pack + hist
// 4 labels/thread via int4. Last-arriving block (across both half-launches)
// reduces g_hist -> g_cnt.
__global__ void __launch_bounds__(PREP_THREADS) k_prep(const int* __restrict__ labels,
                                                       int qoff, int roff) {
    __shared__ int hist[NCLS];
    int t = threadIdx.x;
    if (t < NCLS) hist[t] = 0;
    __syncthreads();
    int q = qoff + blockIdx.x*PREP_THREADS + t;
    int4 lv = ((const int4*)labels)[q];
    uchar4 u;
    u.x = (lv.x >= 0 && lv.x < NCLS) ? (unsigned char)lv.x : (unsigned char)255;
    u.y = (lv.y >= 0 && lv.y < NCLS) ? (unsigned char)lv.y : (unsigned char)255;
    u.z = (lv.z >= 0 && lv.z < NCLS) ? (unsigned char)lv.z : (unsigned char)255;
    u.w = (lv.w >= 0 && lv.w < NCLS) ? (unsigned char)lv.w : (unsigned char)255;
    ((uchar4*)g_labs)[q] = u;
    if (u.x < NCLS) atomicAdd(&hist[u.x], 1);
    if (u.y < NCLS) atomicAdd(&hist[u.y], 1);
    if (u.z < NCLS) atomicAdd(&hist[u.z], 1);
    if (u.w < NCLS) atomicAdd(&hist[u.w], 1);
    __syncthreads();
    if (t < NCLS) g_hist[(roff + blockIdx.x)*NCLS + t] = hist[t];

    __threadfence();
    __shared__ bool isLast;
    if (t == 0) isLast = (atomicAdd(&g_done0, 1u) == PREP_BLOCKS - 1);
    __syncthreads();
    if (!isLast) return;

    __shared__ int scnt[NCLS];
    if (t < NCLS) scnt[t] = 0;
    __syncthreads();
    {
        int loc[NCLS];
        #pragma unroll
        for (int c = 0; c < NCLS; c++) loc[c] = 0;
        const int R = HIST_ROWS / PREP_THREADS;      // 2
        const int* rows = &g_hist[t * R * NCLS];
        for (int r = 0; r < R; r++)
            #pragma unroll
            for (int c = 0; c < NCLS; c++) loc[c] += rows[r*NCLS + c];
        #pragma unroll
        for (int c = 0; c < NCLS; c++) atomicAdd(&scnt[c], loc[c]);
    }
    __syncthreads();
    if (t < NCLS) g_cnt[t] = scnt[t];
    if (t == 0) g_done0 = 0u;
}

// ---------------------------------------------------------------- pass 1
// Segment-sum as GEMM: D[d][c] = sum_p feats[d][p] * onehot(lab[p]==c).
// Per warp: mma.sync.m16n8k16, A = feats [16 dims x 16 px] bf16 loaded
// straight from global in fragment layout, B = onehot built in registers,
// C = fp32 [16 d x 24 cls]. Grid-stride over 4096 chunks of 128 px;
// accumulators persist across chunks; single atomic writeout.
// 4 blocks/SM (55 regs), grid 592 = single wave.
__global__ void __launch_bounds__(P1_THREADS, 4) k_pass1(const float* __restrict__ feats) {
    int w    = threadIdx.x >> 5;
    int lane = threadIdx.x & 31;
    int gid  = lane >> 2;            // 0..7
    int ktid = lane & 3;             // 0..3
    int d_lo = w*16 + gid;

    float c0[4] = {0.f,0.f,0.f,0.f};
    float c1[4] = {0.f,0.f,0.f,0.f};
    float c2[4] = {0.f,0.f,0.f,0.f};

    for (int ch = blockIdx.x; ch < P1_NCHUNK; ch += P1_BLOCKS) {
        int pxg = ch * P1_CHUNK;         // plane-aligned: 128 | 65536
        int b   = pxg >> 16;
        int po  = pxg & 65535;
        const float* rowA = feats + ((size_t)b*DD + d_lo    ) * HWP + po;
        const float* rowB = feats + ((size_t)b*DD + d_lo + 8) * HWP + po;
        const unsigned char* labp = g_labs + pxg;

        #pragma unroll 2
        for (int ks = 0; ks < P1_CHUNK/16; ks++) {
            int p0 = ks*16 + 2*ktid;     // thread's k-anchor within the 16-px tile
            float2 fa0 = *(const float2*)(rowA + p0);        // A[gid][k0,k0+1]
            float2 fa1 = *(const float2*)(rowB + p0);        // A[gid+8][k0,k0+1]
            float2 fa2 = *(const float2*)(rowA + p0 + 8);    // A[gid][k0+8,k0+9]
            float2 fa3 = *(const float2*)(rowB + p0 + 8);    // A[gid+8][k0+8,k0+9]
            unsigned a0, a1, a2, a3;
            asm("cvt.rn.bf16x2.f32 %0, %1, %2;" : "=r"(a0) : "f"(fa0.y), "f"(fa0.x));
            asm("cvt.rn.bf16x2.f32 %0, %1, %2;" : "=r"(a1) : "f"(fa1.y), "f"(fa1.x));
            asm("cvt.rn.bf16x2.f32 %0, %1, %2;" : "=r"(a2) : "f"(fa2.y), "f"(fa2.x));
            asm("cvt.rn.bf16x2.f32 %0, %1, %2;" : "=r"(a3) : "f"(fa3.y), "f"(fa3.x));

            unsigned short L01 = *(const unsigned short*)(labp + p0);
            unsigned short L89 = *(const unsigned short*)(labp + p0 + 8);
            int l0 = L01 & 0xFF, l1 = L01 >> 8;
            int l8 = L89 & 0xFF, l9 = L89 >> 8;

            {   int cls = gid;                       // tile 0: classes 0..7
                unsigned b0 = (l0==cls ? 0x3F80u : 0u) | (l1==cls ? 0x3F800000u : 0u);
                unsigned b1 = (l8==cls ? 0x3F80u : 0u) | (l9==cls ? 0x3F800000u : 0u);
                asm("mma.sync.aligned.m16n8k16.row.col.f32.bf16.bf16.f32 "
                    "{%0,%1,%2,%3}, {%4,%5,%6,%7}, {%8,%9}, {%0,%1,%2,%3};"
                    : "+f"(c0[0]), "+f"(c0[1]), "+f"(c0[2]), "+f"(c0[3])
                    : "r"(a0), "r"(a1), "r"(a2), "r"(a3), "r"(b0), "r"(b1));
            }
            {   int cls = gid + 8;                   // tile 1: classes 8..15
                unsigned b0 = (l0==cls ? 0x3F80u : 0u) | (l1==cls ? 0x3F800000u : 0u);
                unsigned b1 = (l8==cls ? 0x3F80u : 0u) | (l9==cls ? 0x3F800000u : 0u);
                asm("mma.sync.aligned.m16n8k16.row.col.f32.bf16.bf16.f32 "
                    "{%0,%1,%2,%3}, {%4,%5,%6,%7}, {%8,%9}, {%0,%1,%2,%3};"
                    : "+f"(c1[0]), "+f"(c1[1]), "+f"(c1[2]), "+f"(c1[3])
                    : "r"(a0), "r"(a1), "r"(a2), "r"(a3), "r"(b0), "r"(b1));
            }
            {   int cls = gid + 16;                  // tile 2: classes 16..23
                unsigned b0 = (l0==cls ? 0x3F80u : 0u) | (l1==cls ? 0x3F800000u : 0u);
                unsigned b1 = (l8==cls ? 0x3F80u : 0u) | (l9==cls ? 0x3F800000u : 0u);
                asm("mma.sync.aligned.m16n8k16.row.col.f32.bf16.bf16.f32 "
                    "{%0,%1,%2,%3}, {%4,%5,%6,%7}, {%8,%9}, {%0,%1,%2,%3};"
                    : "+f"(c2[0]), "+f"(c2[1]), "+f"(c2[2]), "+f"(c2[3])
                    : "r"(a0), "r"(a1), "r"(a2), "r"(a3), "r"(b0), "r"(b1));
            }
        }
    }

    // writeout: C[m][n] -> d = w*16 + m (m = gid, gid+8), cls = 8t + n
    int dA = w*16 + gid, dB = dA + 8;
    {   int n0 = 2*ktid, n1 = n0 + 1;             // tile 0: cls 0..7
        atomicAdd(&g_sums[n0*DD + dA], c0[0]);
        atomicAdd(&g_sums[n1*DD + dA], c0[1]);
        atomicAdd(&g_sums[n0*DD + dB], c0[2]);
        atomicAdd(&g_sums[n1*DD + dB], c0[3]);
    }
    {   int n0 = 8 + 2*ktid, n1 = n0 + 1;         // tile 1: cls 8..15
        atomicAdd(&g_sums[n0*DD + dA], c1[0]);
        atomicAdd(&g_sums[n1*DD + dA], c1[1]);
        atomicAdd(&g_sums[n0*DD + dB], c1[2]);
        atomicAdd(&g_sums[n1*DD + dB], c1[3]);
    }
    {   int n0 = 16 + 2*ktid, n1 = n0 + 1;        // tile 2: cls 16..23 (keep <19)
        if (n0 < NCLS) { atomicAdd(&g_sums[n0*DD + dA], c2[0]);
                         atomicAdd(&g_sums[n0*DD + dB], c2[2]); }
        if (n1 < NCLS) { atomicAdd(&g_sums[n1*DD + dA], c2[1]);
                         atomicAdd(&g_sums[n1*DD + dB], c2[3]); }
    }
}

// ---------------------------------------------------------------- pass 2
// Each block computes means from g_sums/g_cnt into shared (stride 129,
// conflict-free). Thread pairs split the d-range of each pixel-quad.
// __launch_bounds__(256,7): <=36 regs -> 7 blocks/SM -> 1024 blocks single
// wave. Last-arriving block assembles the final loss and resets scratch.
__global__ void __launch_bounds__(P2_THREADS, 7) k_pass2(const float* __restrict__ feats,
                                                         float* __restrict__ out) {
    __shared__ float ms[NCLS*129];
    __shared__ float vs[NCLS];
    __shared__ float ps[4*P2_QPB];
    int t = threadIdx.x;
    for (int i = t; i < NCLS*DD; i += P2_THREADS) {
        int c = i >> 7;
        ms[c*129 + (i & 127)] = g_sums[i] / fmaxf((float)g_cnt[c], 1.f);
    }
    if (t < NCLS) vs[t] = 0.f;
    __syncthreads();

    int qloc = t & (P2_QPB-1);
    int dh   = t >> 7;                     // 0 or 1
    int q    = blockIdx.x*P2_QPB + qloc;
    int b    = q >> 14;                    // 16384 quads per batch plane
    int hq   = q & 16383;
    const float4* fp = (const float4*)(feats + (size_t)b*DD*HWP + (size_t)dh*64*HWP) + hq;
    uchar4 l = ((const uchar4*)g_labs)[q];

    int l0 = l.x, l1 = l.y, l2 = l.z, l3 = l.w;
    int doff = dh*64;
    const float* m0 = ms + (l0 < NCLS ? l0 : 0)*129 + doff;
    const float* m1 = ms + (l1 < NCLS ? l1 : 0)*129 + doff;
    const float* m2 = ms + (l2 < NCLS ? l2 : 0)*129 + doff;
    const float* m3 = ms + (l3 < NCLS ? l3 : 0)*129 + doff;

    float acc0 = 0.f, acc1 = 0.f, acc2 = 0.f, acc3 = 0.f;
    #pragma unroll 8
    for (int d = 0; d < 64; d++) {
        float4 v = fp[(size_t)d * (HWP/4)];
        float df;
        df = v.x - m0[d]; acc0 = fmaf(df, df, acc0);
        df = v.y - m1[d]; acc1 = fmaf(df, df, acc1);
        df = v.z - m2[d]; acc2 = fmaf(df, df, acc2);
        df = v.w - m3[d]; acc3 = fmaf(df, df, acc3);
    }
    if (dh == 1) {
        ps[0*P2_QPB + qloc] = acc0;
        ps[1*P2_QPB + qloc] = acc1;
        ps[2*P2_QPB + qloc] = acc2;
        ps[3*P2_QPB + qloc] = acc3;
    }
    __syncthreads();
    if (dh == 0) {
        acc0 += ps[0*P2_QPB + qloc];
        acc1 += ps[1*P2_QPB + qloc];
        acc2 += ps[2*P2_QPB + qloc];
        acc3 += ps[3*P2_QPB + qloc];
        if (l0 < NCLS) { float h = fmaxf(sqrtf(acc0) - 0.5f, 0.f); atomicAdd(&vs[l0], h*h); }
        if (l1 < NCLS) { float h = fmaxf(sqrtf(acc1) - 0.5f, 0.f); atomicAdd(&vs[l1], h*h); }
        if (l2 < NCLS) { float h = fmaxf(sqrtf(acc2) - 0.5f, 0.f); atomicAdd(&vs[l2], h*h); }
        if (l3 < NCLS) { float h = fmaxf(sqrtf(acc3) - 0.5f, 0.f); atomicAdd(&vs[l3], h*h); }
    }
    __syncthreads();
    if (t < NCLS) atomicAdd(&g_var[t], vs[t]);

    // ---- last-arriving block: final loss assembly + scratch reset ----
    __threadfence();
    __shared__ bool isLast;
    if (t == 0) isLast = (atomicAdd(&g_done2, 1u) == P2_BLOCKS - 1);
    __syncthreads();
    if (!isLast) return;

    __shared__ float vld[NCLS];
    __shared__ float sreg[NCLS];
    __shared__ float spair[NCLS*NCLS];
    if (t < NCLS) {
        vld[t] = (g_cnt[t] > 100) ? 1.f : 0.f;   // MAX_VIEWS = 100, strict >
        float s = 0.f;
        #pragma unroll 16
        for (int d = 0; d < DD; d++) { float m = ms[t*129 + d]; s = fmaf(m, m, s); }
        sreg[t] = (s > 0.f) ? sqrtf(s) : 0.f;
    }
    for (int idx = t; idx < NCLS*NCLS; idx += P2_THREADS) {
        int a = idx / NCLS, b2 = idx % NCLS;
        float s = 0.f;
        #pragma unroll 16
        for (int d = 0; d < DD; d++) {
            float diff = ms[a*129 + d] - ms[b2*129 + d];
            s = fmaf(diff, diff, s);
        }
        float pdn = (s > 0.f) ? sqrtf(s) : 0.f;
        float hd  = fmaxf(2.f*1.5f - pdn, 0.f);   // 2*DELTA_D
        spair[idx] = hd*hd;
    }
    // reset g_sums for next replay (all pass2 reads of g_sums are done)
    for (int i = t; i < NCLS*DD; i += P2_THREADS) g_sums[i] = 0.f;
    __syncthreads();
    if (t == 0) {
        int last = -1;
        for (int c = 0; c < NCLS; c++) if (vld[c] > 0.f) last = c;
        float tc = 0.f, lvar = 0.f, lreg = 0.f, ldist = 0.f;
        for (int c = 0; c < NCLS; c++) {
            if (vld[c] > 0.f) {
                tc   += 1.f;
                lvar += g_var[c] / fmaxf((float)g_cnt[c], 1.f);
                lreg += sreg[c];
            }
        }
        // faithful buggy double loop: a over all valid, b over valid except
        // the LAST valid class id; includes a == b pairs.
        for (int a = 0; a < NCLS; a++)
            for (int b2 = 0; b2 < NCLS; b2++)
                if (vld[a] > 0.f && vld[b2] > 0.f && b2 != last)
                    ldist += spair[a*NCLS + b2];
        out[0] = lvar/tc + ldist/(tc*(tc - 1.f)) + 0.001f*lreg/tc;  // ALPHA=BETA=1, GAMMA=1e-3
        // reset for next replay
        for (int c = 0; c < NCLS; c++) g_var[c] = 0.f;
        g_done2 = 0u;
    }
}

// ---------------------------------------------------------------- launch
// Launch index 3 (the one ncu captures) = k_pass2.
extern "C" void kernel_launch(void* const* d_in, const int* in_sizes, int n_in,
                              void* d_out, int out_size) {
    const float* feats  = (const float*)d_in[0];
    const int*   labels = (const int*)d_in[1];
    float* out = (float*)d_out;

    k_prep <<<PREP_HALF, PREP_THREADS>>>(labels, 0,    0);          // idx 0
    k_prep <<<PREP_HALF, PREP_THREADS>>>(labels, NQ/2, PREP_HALF);  // idx 1
    k_pass1<<<P1_BLOCKS, P1_THREADS>>>(feats);                      // idx 2
    k_pass2<<<P2_BLOCKS, P2_THREADS>>>(feats, out);                 // idx 3 (profiled)
}

// round 10
// speedup vs baseline: 2.4201x; 1.0390x over previous
#include <cuda_runtime.h>
#include <math.h>

#define NCLS 19
#define DD   128
#define HWP  65536          // H*W
#define BB   8
#define NPIX (BB*HWP)       // 524288
#define NQ   (NPIX/4)       // 131072 pixel-quads

#define P1_BLOCKS  592              // 4 x 148 SMs, single wave
#define P1_THREADS 288              // 8 MMA warps (dims) + 1 label warp
#define P1_CHUNK   128              // pixels per chunk (8 ksteps)
#define P1_NCHUNK  (NPIX/P1_CHUNK)  // 4096

#define P2_THREADS 256
#define P2_QPB     128              // quads per block (d-split pairs)
#define P2_BLOCKS  (NQ/P2_QPB)      // 1024

// ---- static scratch (no allocations allowed; zero-init at load) ----
__device__ float          g_sums[NCLS*DD];
__device__ int            g_cnt[NCLS];
__device__ float          g_var[NCLS];
__device__ unsigned int   g_done2;
__device__ unsigned char  g_labs[NPIX];

// ---------------------------------------------------------------- pass 1
// Segment-sum as GEMM: D[d][c] = sum_p feats[d][p] * onehot(lab[p]==c).
// Warps 0..7: mma.sync.m16n8k16, A = feats [16 dims x 16 px] bf16 loaded
// straight from global in fragment layout (__ldcs, zero reuse), B = onehot
// built in registers from raw int32 labels, C = fp32 [16 d x 24 cls]
// accumulated across all chunks; single atomic writeout.
// Warp 8: reads raw labels (int4), histograms into g_cnt, packs g_labs
// for pass2 (replaces the former prep kernel).
__global__ void __launch_bounds__(P1_THREADS, 4) k_pass1(const float* __restrict__ feats,
                                                         const int* __restrict__ labels) {
    __shared__ int hist[NCLS];
    int w    = threadIdx.x >> 5;
    int lane = threadIdx.x & 31;

    if (w == 8) {
        // ---------------- label warp: histogram + pack ----------------
        if (lane < NCLS) hist[lane] = 0;
        __syncwarp();
        for (int ch = blockIdx.x; ch < P1_NCHUNK; ch += P1_BLOCKS) {
            int pxg = ch * P1_CHUNK;
            int4 lv = ((const int4*)(labels + pxg))[lane];   // 4 labels/lane
            uchar4 u;
            u.x = (lv.x >= 0 && lv.x < NCLS) ? (unsigned char)lv.x : (unsigned char)255;
            u.y = (lv.y >= 0 && lv.y < NCLS) ? (unsigned char)lv.y : (unsigned char)255;
            u.z = (lv.z >= 0 && lv.z < NCLS) ? (unsigned char)lv.z : (unsigned char)255;
            u.w = (lv.w >= 0 && lv.w < NCLS) ? (unsigned char)lv.w : (unsigned char)255;
            ((uchar4*)(g_labs + pxg))[lane] = u;
            if (u.x < NCLS) atomicAdd(&hist[u.x], 1);
            if (u.y < NCLS) atomicAdd(&hist[u.y], 1);
            if (u.z < NCLS) atomicAdd(&hist[u.z], 1);
            if (u.w < NCLS) atomicAdd(&hist[u.w], 1);
        }
        __syncwarp();
        if (lane < NCLS) atomicAdd(&g_cnt[lane], hist[lane]);
        return;
    }

    // ---------------- MMA warps: segment-sum GEMM ----------------
    int gid  = lane >> 2;            // 0..7
    int ktid = lane & 3;             // 0..3
    int d_lo = w*16 + gid;

    float c0[4] = {0.f,0.f,0.f,0.f};
    float c1[4] = {0.f,0.f,0.f,0.f};
    float c2[4] = {0.f,0.f,0.f,0.f};

    for (int ch = blockIdx.x; ch < P1_NCHUNK; ch += P1_BLOCKS) {
        int pxg = ch * P1_CHUNK;         // plane-aligned: 128 | 65536
        int b   = pxg >> 16;
        int po  = pxg & 65535;
        const float* rowA = feats + ((size_t)b*DD + d_lo    ) * HWP + po;
        const float* rowB = feats + ((size_t)b*DD + d_lo + 8) * HWP + po;
        const int*   labp = labels + pxg;

        #pragma unroll 2
        for (int ks = 0; ks < P1_CHUNK/16; ks++) {
            int p0 = ks*16 + 2*ktid;     // thread's k-anchor within the 16-px tile
            float2 fa0 = __ldcs((const float2*)(rowA + p0));        // A[gid][k0,k0+1]
            float2 fa1 = __ldcs((const float2*)(rowB + p0));        // A[gid+8][k0,k0+1]
            float2 fa2 = __ldcs((const float2*)(rowA + p0 + 8));    // A[gid][k0+8,k0+9]
            float2 fa3 = __ldcs((const float2*)(rowB + p0 + 8));    // A[gid+8][k0+8,k0+9]
            unsigned a0, a1, a2, a3;
            asm("cvt.rn.bf16x2.f32 %0, %1, %2;" : "=r"(a0) : "f"(fa0.y), "f"(fa0.x));
            asm("cvt.rn.bf16x2.f32 %0, %1, %2;" : "=r"(a1) : "f"(fa1.y), "f"(fa1.x));
            asm("cvt.rn.bf16x2.f32 %0, %1, %2;" : "=r"(a2) : "f"(fa2.y), "f"(fa2.x));
            asm("cvt.rn.bf16x2.f32 %0, %1, %2;" : "=r"(a3) : "f"(fa3.y), "f"(fa3.x));

            int2 L01 = *(const int2*)(labp + p0);       // L1/L2 hit (8 warps share)
            int2 L89 = *(const int2*)(labp + p0 + 8);
            int l0 = L01.x, l1 = L01.y;
            int l8 = L89.x, l9 = L89.y;

            {   int cls = gid;                       // tile 0: classes 0..7
                unsigned b0 = (l0==cls ? 0x3F80u : 0u) | (l1==cls ? 0x3F800000u : 0u);
                unsigned b1 = (l8==cls ? 0x3F80u : 0u) | (l9==cls ? 0x3F800000u : 0u);
                asm("mma.sync.aligned.m16n8k16.row.col.f32.bf16.bf16.f32 "
                    "{%0,%1,%2,%3}, {%4,%5,%6,%7}, {%8,%9}, {%0,%1,%2,%3};"
                    : "+f"(c0[0]), "+f"(c0[1]), "+f"(c0[2]), "+f"(c0[3])
                    : "r"(a0), "r"(a1), "r"(a2), "r"(a3), "r"(b0), "r"(b1));
            }
            {   int cls = gid + 8;                   // tile 1: classes 8..15
                unsigned b0 = (l0==cls ? 0x3F80u : 0u) | (l1==cls ? 0x3F800000u : 0u);
                unsigned b1 = (l8==cls ? 0x3F80u : 0u) | (l9==cls ? 0x3F800000u : 0u);
                asm("mma.sync.aligned.m16n8k16.row.col.f32.bf16.bf16.f32 "
                    "{%0,%1,%2,%3}, {%4,%5,%6,%7}, {%8,%9}, {%0,%1,%2,%3};"
                    : "+f"(c1[0]), "+f"(c1[1]), "+f"(c1[2]), "+f"(c1[3])
                    : "r"(a0), "r"(a1), "r"(a2), "r"(a3), "r"(b0), "r"(b1));
            }
            {   int cls = gid + 16;                  // tile 2: classes 16..23
                unsigned b0 = (l0==cls ? 0x3F80u : 0u) | (l1==cls ? 0x3F800000u : 0u);
                unsigned b1 = (l8==cls ? 0x3F80u : 0u) | (l9==cls ? 0x3F800000u : 0u);
                asm("mma.sync.aligned.m16n8k16.row.col.f32.bf16.bf16.f32 "
                    "{%0,%1,%2,%3}, {%4,%5,%6,%7}, {%8,%9}, {%0,%1,%2,%3};"
                    : "+f"(c2[0]), "+f"(c2[1]), "+f"(c2[2]), "+f"(c2[3])
                    : "r"(a0), "r"(a1), "r"(a2), "r"(a3), "r"(b0), "r"(b1));
            }
        }
    }

    // writeout: C[m][n] -> d = w*16 + m (m = gid, gid+8), cls = 8t + n
    int dA = w*16 + gid, dB = dA + 8;
    {   int n0 = 2*ktid, n1 = n0 + 1;             // tile 0: cls 0..7
        atomicAdd(&g_sums[n0*DD + dA], c0[0]);
        atomicAdd(&g_sums[n1*DD + dA], c0[1]);
        atomicAdd(&g_sums[n0*DD + dB], c0[2]);
        atomicAdd(&g_sums[n1*DD + dB], c0[3]);
    }
    {   int n0 = 8 + 2*ktid, n1 = n0 + 1;         // tile 1: cls 8..15
        atomicAdd(&g_sums[n0*DD + dA], c1[0]);
        atomicAdd(&g_sums[n1*DD + dA], c1[1]);
        atomicAdd(&g_sums[n0*DD + dB], c1[2]);
        atomicAdd(&g_sums[n1*DD + dB], c1[3]);
    }
    {   int n0 = 16 + 2*ktid, n1 = n0 + 1;        // tile 2: cls 16..23 (keep <19)
        if (n0 < NCLS) { atomicAdd(&g_sums[n0*DD + dA], c2[0]);
                         atomicAdd(&g_sums[n0*DD + dB], c2[2]); }
        if (n1 < NCLS) { atomicAdd(&g_sums[n1*DD + dA], c2[1]);
                         atomicAdd(&g_sums[n1*DD + dB], c2[3]); }
    }
}

// ---------------------------------------------------------------- pass 2
// Each block computes means from g_sums/g_cnt into shared (stride 129,
// conflict-free). Thread pairs split the d-range of each pixel-quad.
// unroll 16 + __ldcs streaming loads (zero reuse -> bypass L1 allocation).
// __launch_bounds__(256,7): 7 blocks/SM -> 1024 blocks single wave.
// Last-arriving block assembles the final loss and resets ALL scratch.
__global__ void __launch_bounds__(P2_THREADS, 7) k_pass2(const float* __restrict__ feats,
                                                         float* __restrict__ out) {
    __shared__ float ms[NCLS*129];
    __shared__ float vs[NCLS];
    __shared__ float ps[4*P2_QPB];
    int t = threadIdx.x;
    for (int i = t; i < NCLS*DD; i += P2_THREADS) {
        int c = i >> 7;
        ms[c*129 + (i & 127)] = g_sums[i] / fmaxf((float)g_cnt[c], 1.f);
    }
    if (t < NCLS) vs[t] = 0.f;
    __syncthreads();

    int qloc = t & (P2_QPB-1);
    int dh   = t >> 7;                     // 0 or 1
    int q    = blockIdx.x*P2_QPB + qloc;
    int b    = q >> 14;                    // 16384 quads per batch plane
    int hq   = q & 16383;
    const float4* fp = (const float4*)(feats + (size_t)b*DD*HWP + (size_t)dh*64*HWP) + hq;
    uchar4 l = ((const uchar4*)g_labs)[q];

    int l0 = l.x, l1 = l.y, l2 = l.z, l3 = l.w;
    int doff = dh*64;
    const float* m0 = ms + (l0 < NCLS ? l0 : 0)*129 + doff;
    const float* m1 = ms + (l1 < NCLS ? l1 : 0)*129 + doff;
    const float* m2 = ms + (l2 < NCLS ? l2 : 0)*129 + doff;
    const float* m3 = ms + (l3 < NCLS ? l3 : 0)*129 + doff;

    float acc0 = 0.f, acc1 = 0.f, acc2 = 0.f, acc3 = 0.f;
    #pragma unroll 16
    for (int d = 0; d < 64; d++) {
        float4 v = __ldcs(fp + (size_t)d * (HWP/4));
        float df;
        df = v.x - m0[d]; acc0 = fmaf(df, df, acc0);
        df = v.y - m1[d]; acc1 = fmaf(df, df, acc1);
        df = v.z - m2[d]; acc2 = fmaf(df, df, acc2);
        df = v.w - m3[d]; acc3 = fmaf(df, df, acc3);
    }
    if (dh == 1) {
        ps[0*P2_QPB + qloc] = acc0;
        ps[1*P2_QPB + qloc] = acc1;
        ps[2*P2_QPB + qloc] = acc2;
        ps[3*P2_QPB + qloc] = acc3;
    }
    __syncthreads();
    if (dh == 0) {
        acc0 += ps[0*P2_QPB + qloc];
        acc1 += ps[1*P2_QPB + qloc];
        acc2 += ps[2*P2_QPB + qloc];
        acc3 += ps[3*P2_QPB + qloc];
        if (l0 < NCLS) { float h = fmaxf(sqrtf(acc0) - 0.5f, 0.f); atomicAdd(&vs[l0], h*h); }
        if (l1 < NCLS) { float h = fmaxf(sqrtf(acc1) - 0.5f, 0.f); atomicAdd(&vs[l1], h*h); }
        if (l2 < NCLS) { float h = fmaxf(sqrtf(acc2) - 0.5f, 0.f); atomicAdd(&vs[l2], h*h); }
        if (l3 < NCLS) { float h = fmaxf(sqrtf(acc3) - 0.5f, 0.f); atomicAdd(&vs[l3], h*h); }
    }
    __syncthreads();
    if (t < NCLS) atomicAdd(&g_var[t], vs[t]);

    // ---- last-arriving block: final loss assembly + scratch reset ----
    __threadfence();
    __shared__ bool isLast;
    if (t == 0) isLast = (atomicAdd(&g_done2, 1u) == P2_BLOCKS - 1);
    __syncthreads();
    if (!isLast) return;

    __shared__ float vld[NCLS];
    __shared__ float sreg[NCLS];
    __shared__ float spair[NCLS*NCLS];
    if (t < NCLS) {
        vld[t] = (g_cnt[t] > 100) ? 1.f : 0.f;   // MAX_VIEWS = 100, strict >
        float s = 0.f;
        #pragma unroll 16
        for (int d = 0; d < DD; d++) { float m = ms[t*129 + d]; s = fmaf(m, m, s); }
        sreg[t] = (s > 0.f) ? sqrtf(s) : 0.f;
    }
    for (int idx = t; idx < NCLS*NCLS; idx += P2_THREADS) {
        int a = idx / NCLS, b2 = idx % NCLS;
        float s = 0.f;
        #pragma unroll 16
        for (int d = 0; d < DD; d++) {
            float diff = ms[a*129 + d] - ms[b2*129 + d];
            s = fmaf(diff, diff, s);
        }
        float pdn = (s > 0.f) ? sqrtf(s) : 0.f;
        float hd  = fmaxf(2.f*1.5f - pdn, 0.f);   // 2*DELTA_D
        spair[idx] = hd*hd;
    }
    // reset g_sums for next replay (all pass2 reads of g_sums are done)
    for (int i = t; i < NCLS*DD; i += P2_THREADS) g_sums[i] = 0.f;
    __syncthreads();
    if (t == 0) {
        int last = -1;
        for (int c = 0; c < NCLS; c++) if (vld[c] > 0.f) last = c;
        float tc = 0.f, lvar = 0.f, lreg = 0.f, ldist = 0.f;
        for (int c = 0; c < NCLS; c++) {
            if (vld[c] > 0.f) {
                tc   += 1.f;
                lvar += g_var[c] / fmaxf((float)g_cnt[c], 1.f);
                lreg += sreg[c];
            }
        }
        // faithful buggy double loop: a over all valid, b over valid except
        // the LAST valid class id; includes a == b pairs.
        for (int a = 0; a < NCLS; a++)
            for (int b2 = 0; b2 < NCLS; b2++)
                if (vld[a] > 0.f && vld[b2] > 0.f && b2 != last)
                    ldist += spair[a*NCLS + b2];
        out[0] = lvar/tc + ldist/(tc*(tc - 1.f)) + 0.001f*lreg/tc;  // ALPHA=BETA=1, GAMMA=1e-3
        // reset for next replay (g_cnt is re-accumulated by pass1)
        for (int c = 0; c < NCLS; c++) { g_var[c] = 0.f; g_cnt[c] = 0; }
        g_done2 = 0u;
    }
}

// ---------------------------------------------------------------- launch
extern "C" void kernel_launch(void* const* d_in, const int* in_sizes, int n_in,
                              void* d_out, int out_size) {
    const float* feats  = (const float*)d_in[0];
    const int*   labels = (const int*)d_in[1];
    float* out = (float*)d_out;

    k_pass1<<<P1_BLOCKS, P1_THREADS>>>(feats, labels);
    k_pass2<<<P2_BLOCKS, P2_THREADS>>>(feats, out);
}

// round 11
// speedup vs baseline: 2.4691x; 1.0202x over previous
#include <cuda_runtime.h>
#include <math.h>

#define NCLS 19
#define DD   128
#define HWP  65536          // H*W
#define BB   8
#define NPIX (BB*HWP)       // 524288
#define NQ   (NPIX/4)       // 131072 pixel-quads

#define P1_BLOCKS  592              // 4 x 148 SMs, single wave
#define P1_THREADS 288              // 8 MMA warps (dims) + 1 label warp
#define P1_CHUNK   128              // pixels per chunk (8 ksteps)
#define P1_NCHUNK  (NPIX/P1_CHUNK)  // 4096

#define P2_THREADS 256
#define P2_PXB     512              // pixels per block (2 px per thread)
#define P2_BLOCKS  (NPIX/P2_PXB)    // 1024

// ---- static scratch (no allocations allowed; zero-init at load) ----
__device__ float          g_sums[NCLS*DD];
__device__ int            g_cnt[NCLS];
__device__ float          g_var[NCLS];
__device__ unsigned int   g_done2;
__device__ unsigned char  g_labs[NPIX];

// ---------------------------------------------------------------- pass 1
// Segment-sum as GEMM: D[d][c] = sum_p feats[d][p] * onehot(lab[p]==c).
// Warps 0..7: mma.sync.m16n8k16, A = feats [16 dims x 16 px] bf16 loaded
// straight from global in fragment layout (__ldcs, zero reuse), B = onehot
// built in registers from raw int32 labels, C = fp32 [16 d x 24 cls]
// accumulated across all chunks; single atomic writeout.
// Warp 8: reads raw labels (int4), histograms into g_cnt, packs g_labs.
__global__ void __launch_bounds__(P1_THREADS, 4) k_pass1(const float* __restrict__ feats,
                                                         const int* __restrict__ labels) {
    __shared__ int hist[NCLS];
    int w    = threadIdx.x >> 5;
    int lane = threadIdx.x & 31;

    if (w == 8) {
        // ---------------- label warp: histogram + pack ----------------
        if (lane < NCLS) hist[lane] = 0;
        __syncwarp();
        for (int ch = blockIdx.x; ch < P1_NCHUNK; ch += P1_BLOCKS) {
            int pxg = ch * P1_CHUNK;
            int4 lv = ((const int4*)(labels + pxg))[lane];   // 4 labels/lane
            uchar4 u;
            u.x = (lv.x >= 0 && lv.x < NCLS) ? (unsigned char)lv.x : (unsigned char)255;
            u.y = (lv.y >= 0 && lv.y < NCLS) ? (unsigned char)lv.y : (unsigned char)255;
            u.z = (lv.z >= 0 && lv.z < NCLS) ? (unsigned char)lv.z : (unsigned char)255;
            u.w = (lv.w >= 0 && lv.w < NCLS) ? (unsigned char)lv.w : (unsigned char)255;
            ((uchar4*)(g_labs + pxg))[lane] = u;
            if (u.x < NCLS) atomicAdd(&hist[u.x], 1);
            if (u.y < NCLS) atomicAdd(&hist[u.y], 1);
            if (u.z < NCLS) atomicAdd(&hist[u.z], 1);
            if (u.w < NCLS) atomicAdd(&hist[u.w], 1);
        }
        __syncwarp();
        if (lane < NCLS) atomicAdd(&g_cnt[lane], hist[lane]);
        return;
    }

    // ---------------- MMA warps: segment-sum GEMM ----------------
    int gid  = lane >> 2;            // 0..7
    int ktid = lane & 3;             // 0..3
    int d_lo = w*16 + gid;

    float c0[4] = {0.f,0.f,0.f,0.f};
    float c1[4] = {0.f,0.f,0.f,0.f};
    float c2[4] = {0.f,0.f,0.f,0.f};

    for (int ch = blockIdx.x; ch < P1_NCHUNK; ch += P1_BLOCKS) {
        int pxg = ch * P1_CHUNK;         // plane-aligned: 128 | 65536
        int b   = pxg >> 16;
        int po  = pxg & 65535;
        const float* rowA = feats + ((size_t)b*DD + d_lo    ) * HWP + po;
        const float* rowB = feats + ((size_t)b*DD + d_lo + 8) * HWP + po;
        const int*   labp = labels + pxg;

        #pragma unroll 2
        for (int ks = 0; ks < P1_CHUNK/16; ks++) {
            int p0 = ks*16 + 2*ktid;     // thread's k-anchor within the 16-px tile
            float2 fa0 = __ldcs((const float2*)(rowA + p0));        // A[gid][k0,k0+1]
            float2 fa1 = __ldcs((const float2*)(rowB + p0));        // A[gid+8][k0,k0+1]
            float2 fa2 = __ldcs((const float2*)(rowA + p0 + 8));    // A[gid][k0+8,k0+9]
            float2 fa3 = __ldcs((const float2*)(rowB + p0 + 8));    // A[gid+8][k0+8,k0+9]
            unsigned a0, a1, a2, a3;
            asm("cvt.rn.bf16x2.f32 %0, %1, %2;" : "=r"(a0) : "f"(fa0.y), "f"(fa0.x));
            asm("cvt.rn.bf16x2.f32 %0, %1, %2;" : "=r"(a1) : "f"(fa1.y), "f"(fa1.x));
            asm("cvt.rn.bf16x2.f32 %0, %1, %2;" : "=r"(a2) : "f"(fa2.y), "f"(fa2.x));
            asm("cvt.rn.bf16x2.f32 %0, %1, %2;" : "=r"(a3) : "f"(fa3.y), "f"(fa3.x));

            int2 L01 = *(const int2*)(labp + p0);       // L1/L2 hit (8 warps share)
            int2 L89 = *(const int2*)(labp + p0 + 8);
            int l0 = L01.x, l1 = L01.y;
            int l8 = L89.x, l9 = L89.y;

            {   int cls = gid;                       // tile 0: classes 0..7
                unsigned b0 = (l0==cls ? 0x3F80u : 0u) | (l1==cls ? 0x3F800000u : 0u);
                unsigned b1 = (l8==cls ? 0x3F80u : 0u) | (l9==cls ? 0x3F800000u : 0u);
                asm("mma.sync.aligned.m16n8k16.row.col.f32.bf16.bf16.f32 "
                    "{%0,%1,%2,%3}, {%4,%5,%6,%7}, {%8,%9}, {%0,%1,%2,%3};"
                    : "+f"(c0[0]), "+f"(c0[1]), "+f"(c0[2]), "+f"(c0[3])
                    : "r"(a0), "r"(a1), "r"(a2), "r"(a3), "r"(b0), "r"(b1));
            }
            {   int cls = gid + 8;                   // tile 1: classes 8..15
                unsigned b0 = (l0==cls ? 0x3F80u : 0u) | (l1==cls ? 0x3F800000u : 0u);
                unsigned b1 = (l8==cls ? 0x3F80u : 0u) | (l9==cls ? 0x3F800000u : 0u);
                asm("mma.sync.aligned.m16n8k16.row.col.f32.bf16.bf16.f32 "
                    "{%0,%1,%2,%3}, {%4,%5,%6,%7}, {%8,%9}, {%0,%1,%2,%3};"
                    : "+f"(c1[0]), "+f"(c1[1]), "+f"(c1[2]), "+f"(c1[3])
                    : "r"(a0), "r"(a1), "r"(a2), "r"(a3), "r"(b0), "r"(b1));
            }
            {   int cls = gid + 16;                  // tile 2: classes 16..23
                unsigned b0 = (l0==cls ? 0x3F80u : 0u) | (l1==cls ? 0x3F800000u : 0u);
                unsigned b1 = (l8==cls ? 0x3F80u : 0u) | (l9==cls ? 0x3F800000u : 0u);
                asm("mma.sync.aligned.m16n8k16.row.col.f32.bf16.bf16.f32 "
                    "{%0,%1,%2,%3}, {%4,%5,%6,%7}, {%8,%9}, {%0,%1,%2,%3};"
                    : "+f"(c2[0]), "+f"(c2[1]), "+f"(c2[2]), "+f"(c2[3])
                    : "r"(a0), "r"(a1), "r"(a2), "r"(a3), "r"(b0), "r"(b1));
            }
        }
    }

    // writeout: C[m][n] -> d = w*16 + m (m = gid, gid+8), cls = 8t + n
    int dA = w*16 + gid, dB = dA + 8;
    {   int n0 = 2*ktid, n1 = n0 + 1;             // tile 0: cls 0..7
        atomicAdd(&g_sums[n0*DD + dA], c0[0]);
        atomicAdd(&g_sums[n1*DD + dA], c0[1]);
        atomicAdd(&g_sums[n0*DD + dB], c0[2]);
        atomicAdd(&g_sums[n1*DD + dB], c0[3]);
    }
    {   int n0 = 8 + 2*ktid, n1 = n0 + 1;         // tile 1: cls 8..15
        atomicAdd(&g_sums[n0*DD + dA], c1[0]);
        atomicAdd(&g_sums[n1*DD + dA], c1[1]);
        atomicAdd(&g_sums[n0*DD + dB], c1[2]);
        atomicAdd(&g_sums[n1*DD + dB], c1[3]);
    }
    {   int n0 = 16 + 2*ktid, n1 = n0 + 1;        // tile 2: cls 16..23 (keep <19)
        if (n0 < NCLS) { atomicAdd(&g_sums[n0*DD + dA], c2[0]);
                         atomicAdd(&g_sums[n0*DD + dB], c2[2]); }
        if (n1 < NCLS) { atomicAdd(&g_sums[n1*DD + dA], c2[1]);
                         atomicAdd(&g_sums[n1*DD + dB], c2[3]); }
    }
}

// ---------------------------------------------------------------- pass 2
// Pass1-shaped reader: each thread owns a PIXEL PAIR (float2 loads; a warp
// covers 64 contiguous px = 256B per plane) and walks d in 32 iterations,
// loading 4 planes concurrently (d, d+32, d+64, d+96) -> 4 pages in flight
// per thread at ~8 regs of data. No d-split, no shared combine.
// Means in shared at stride 129 (distinct labels -> distinct banks).
// 1024 blocks, 7/SM -> single wave. Last block assembles the loss.
__global__ void __launch_bounds__(P2_THREADS, 7) k_pass2(const float* __restrict__ feats,
                                                         float* __restrict__ out) {
    __shared__ float ms[NCLS*129];
    __shared__ float vs[NCLS];
    int t = threadIdx.x;
    for (int i = t; i < NCLS*DD; i += P2_THREADS) {
        int c = i >> 7;
        ms[c*129 + (i & 127)] = g_sums[i] / fmaxf((float)g_cnt[c], 1.f);
    }
    if (t < NCLS) vs[t] = 0.f;
    __syncthreads();

    int px = blockIdx.x*P2_PXB + 2*t;      // even; block is plane-aligned (512 | 65536)
    int b  = px >> 16;
    int po = px & 65535;
    const float* fb = feats + (size_t)b*DD*HWP + po;   // plane d at fb + d*HWP

    uchar2 l2 = *(const uchar2*)(g_labs + px);
    int l0 = l2.x, l1 = l2.y;
    const float* mr0 = ms + (l0 < NCLS ? l0 : 0)*129;
    const float* mr1 = ms + (l1 < NCLS ? l1 : 0)*129;

    float acc0 = 0.f, acc1 = 0.f;
    #pragma unroll 4
    for (int d = 0; d < 32; d++) {
        float2 v0 = *(const float2*)(fb + (size_t)(d     )*HWP);
        float2 v1 = *(const float2*)(fb + (size_t)(d + 32)*HWP);
        float2 v2 = *(const float2*)(fb + (size_t)(d + 64)*HWP);
        float2 v3 = *(const float2*)(fb + (size_t)(d + 96)*HWP);
        float df;
        df = v0.x - mr0[d     ]; acc0 = fmaf(df, df, acc0);
        df = v1.x - mr0[d + 32]; acc0 = fmaf(df, df, acc0);
        df = v2.x - mr0[d + 64]; acc0 = fmaf(df, df, acc0);
        df = v3.x - mr0[d + 96]; acc0 = fmaf(df, df, acc0);
        df = v0.y - mr1[d     ]; acc1 = fmaf(df, df, acc1);
        df = v1.y - mr1[d + 32]; acc1 = fmaf(df, df, acc1);
        df = v2.y - mr1[d + 64]; acc1 = fmaf(df, df, acc1);
        df = v3.y - mr1[d + 96]; acc1 = fmaf(df, df, acc1);
    }
    if (l0 < NCLS) { float h = fmaxf(sqrtf(acc0) - 0.5f, 0.f); atomicAdd(&vs[l0], h*h); }
    if (l1 < NCLS) { float h = fmaxf(sqrtf(acc1) - 0.5f, 0.f); atomicAdd(&vs[l1], h*h); }
    __syncthreads();
    if (t < NCLS) atomicAdd(&g_var[t], vs[t]);

    // ---- last-arriving block: final loss assembly + scratch reset ----
    __threadfence();
    __shared__ bool isLast;
    if (t == 0) isLast = (atomicAdd(&g_done2, 1u) == P2_BLOCKS - 1);
    __syncthreads();
    if (!isLast) return;

    __shared__ float vld[NCLS];
    __shared__ float sreg[NCLS];
    __shared__ float spair[NCLS*NCLS];
    if (t < NCLS) {
        vld[t] = (g_cnt[t] > 100) ? 1.f : 0.f;   // MAX_VIEWS = 100, strict >
        float s = 0.f;
        #pragma unroll 16
        for (int d = 0; d < DD; d++) { float m = ms[t*129 + d]; s = fmaf(m, m, s); }
        sreg[t] = (s > 0.f) ? sqrtf(s) : 0.f;
    }
    for (int idx = t; idx < NCLS*NCLS; idx += P2_THREADS) {
        int a = idx / NCLS, b2 = idx % NCLS;
        float s = 0.f;
        #pragma unroll 16
        for (int d = 0; d < DD; d++) {
            float diff = ms[a*129 + d] - ms[b2*129 + d];
            s = fmaf(diff, diff, s);
        }
        float pdn = (s > 0.f) ? sqrtf(s) : 0.f;
        float hd  = fmaxf(2.f*1.5f - pdn, 0.f);   // 2*DELTA_D
        spair[idx] = hd*hd;
    }
    // reset g_sums for next replay (all pass2 reads of g_sums are done)
    for (int i = t; i < NCLS*DD; i += P2_THREADS) g_sums[i] = 0.f;
    __syncthreads();
    if (t == 0) {
        int last = -1;
        for (int c = 0; c < NCLS; c++) if (vld[c] > 0.f) last = c;
        float tc = 0.f, lvar = 0.f, lreg = 0.f, ldist = 0.f;
        for (int c = 0; c < NCLS; c++) {
            if (vld[c] > 0.f) {
                tc   += 1.f;
                lvar += g_var[c] / fmaxf((float)g_cnt[c], 1.f);
                lreg += sreg[c];
            }
        }
        // faithful buggy double loop: a over all valid, b over valid except
        // the LAST valid class id; includes a == b pairs.
        for (int a = 0; a < NCLS; a++)
            for (int b2 = 0; b2 < NCLS; b2++)
                if (vld[a] > 0.f && vld[b2] > 0.f && b2 != last)
                    ldist += spair[a*NCLS + b2];
        out[0] = lvar/tc + ldist/(tc*(tc - 1.f)) + 0.001f*lreg/tc;  // ALPHA=BETA=1, GAMMA=1e-3
        // reset for next replay (g_cnt is re-accumulated by pass1)
        for (int c = 0; c < NCLS; c++) { g_var[c] = 0.f; g_cnt[c] = 0; }
        g_done2 = 0u;
    }
}

// ---------------------------------------------------------------- launch
extern "C" void kernel_launch(void* const* d_in, const int* in_sizes, int n_in,
                              void* d_out, int out_size) {
    const float* feats  = (const float*)d_in[0];
    const int*   labels = (const int*)d_in[1];
    float* out = (float*)d_out;

    k_pass1<<<P1_BLOCKS, P1_THREADS>>>(feats, labels);
    k_pass2<<<P2_BLOCKS, P2_THREADS>>>(feats, out);
}